// round 3
// baseline (speedup 1.0000x reference)
#include <cuda_runtime.h>
#include <math.h>

#define BB 16
#define NN 1029
#define HH 16
#define HDIM 64
#define DD 1024
#define MT (BB*NN)          // 16464 rows
#define NP 1024             // rope table length
#define PREFIX (NN-NP)      // 5

// ---------------- scratch (no allocations allowed) ----------------
__device__ float g_q[(size_t)BB*HH*NN*HDIM];
__device__ float g_k[(size_t)BB*HH*NN*HDIM];
__device__ float g_v[(size_t)BB*HH*NN*HDIM];
__device__ float g_ctx[(size_t)BB*NN*DD];

// ---------------- GEMM: Y[m,n] = sum_k X[m,k]*W[n,k] + bias[n] ----------------
// MODE 0: plain row-major (M x D) output
// MODE 1: write to (B,H,N,HD) head layout
template<int MODE>
__global__ __launch_bounds__(256)
void gemm_kernel(const float* __restrict__ X, const float* __restrict__ W,
                 const float* __restrict__ bias, float* __restrict__ Y)
{
    __shared__ __align__(16) float As[8][128];
    __shared__ __align__(16) float Bs[8][128];

    const int bm = blockIdx.y * 128;
    const int bn = blockIdx.x * 128;
    const int tid = threadIdx.x;
    const int tx = tid & 15;         // 0..15  -> n micro tile
    const int ty = tid >> 4;         // 0..15  -> m micro tile

    float acc[8][8];
#pragma unroll
    for (int i = 0; i < 8; i++)
#pragma unroll
        for (int j = 0; j < 8; j++) acc[i][j] = 0.f;

    const int lrow = tid >> 1;          // 0..127
    const int lk4  = (tid & 1) * 4;     // 0 or 4

    for (int k0 = 0; k0 < DD; k0 += 8) {
        float4 a4 = make_float4(0.f, 0.f, 0.f, 0.f);
        const int gm = bm + lrow;
        if (gm < MT)
            a4 = *reinterpret_cast<const float4*>(X + (size_t)gm * DD + k0 + lk4);
        const float4 b4 = *reinterpret_cast<const float4*>(W + (size_t)(bn + lrow) * DD + k0 + lk4);

        As[lk4 + 0][lrow] = a4.x; As[lk4 + 1][lrow] = a4.y;
        As[lk4 + 2][lrow] = a4.z; As[lk4 + 3][lrow] = a4.w;
        Bs[lk4 + 0][lrow] = b4.x; Bs[lk4 + 1][lrow] = b4.y;
        Bs[lk4 + 2][lrow] = b4.z; Bs[lk4 + 3][lrow] = b4.w;
        __syncthreads();

#pragma unroll
        for (int kk = 0; kk < 8; kk++) {
            float ar[8], br[8];
            *reinterpret_cast<float4*>(ar)     = *reinterpret_cast<const float4*>(&As[kk][ty * 8]);
            *reinterpret_cast<float4*>(ar + 4) = *reinterpret_cast<const float4*>(&As[kk][ty * 8 + 4]);
            *reinterpret_cast<float4*>(br)     = *reinterpret_cast<const float4*>(&Bs[kk][tx * 8]);
            *reinterpret_cast<float4*>(br + 4) = *reinterpret_cast<const float4*>(&Bs[kk][tx * 8 + 4]);
#pragma unroll
            for (int i = 0; i < 8; i++)
#pragma unroll
                for (int j = 0; j < 8; j++)
                    acc[i][j] = fmaf(ar[i], br[j], acc[i][j]);
        }
        __syncthreads();
    }

#pragma unroll
    for (int i = 0; i < 8; i++) {
        const int gm = bm + ty * 8 + i;
        if (gm >= MT) continue;
        const int bb = gm / NN;
        const int nn = gm - bb * NN;
#pragma unroll
        for (int j = 0; j < 8; j++) {
            const int gn = bn + tx * 8 + j;
            const float val = acc[i][j] + bias[gn];
            if (MODE == 0) {
                Y[(size_t)gm * DD + gn] = val;
            } else {
                const int h  = gn >> 6;
                const int hd = gn & 63;
                Y[(((size_t)(bb * HH + h)) * NN + nn) * HDIM + hd] = val;
            }
        }
    }
}

// ---------------- RoPE on q and k (in-place, rows n >= PREFIX) ----------------
__global__ __launch_bounds__(256)
void rope_kernel(const float* __restrict__ sinp, const float* __restrict__ cosp)
{
    const int idx = blockIdx.x * blockDim.x + threadIdx.x;
    const int total = BB * HH * NP * 32;
    if (idx >= total) return;
    const int d  = idx & 31;
    const int r  = idx >> 5;
    const int n  = r % NP;
    const int bh = r / NP;
    const size_t base = ((size_t)bh * NN + (n + PREFIX)) * HDIM;

    const float c1 = cosp[n * HDIM + d];
    const float c2 = cosp[n * HDIM + d + 32];
    const float s1 = sinp[n * HDIM + d];
    const float s2 = sinp[n * HDIM + d + 32];

    const float q1 = g_q[base + d], q2 = g_q[base + d + 32];
    g_q[base + d]      = q1 * c1 - q2 * s1;
    g_q[base + d + 32] = q2 * c2 + q1 * s2;

    const float k1 = g_k[base + d], k2 = g_k[base + d + 32];
    g_k[base + d]      = k1 * c1 - k2 * s1;
    g_k[base + d + 32] = k2 * c2 + k1 * s2;
}

// ---------------- Flash attention: per (b,h), 64 q-rows per CTA ----------------
#define BQ 64
#define BKT 32

__global__ __launch_bounds__(128)
void attn_kernel(float* __restrict__ ctx)
{
    __shared__ __align__(16) float Qs[BQ][HDIM + 4];   // pad 68 -> 2-way max
    __shared__ __align__(16) float Ks[BKT][HDIM];
    __shared__ __align__(16) float Vs[BKT][HDIM];
    __shared__ float Ss[BQ][BKT + 1];

    const int tid = threadIdx.x;          // 128
    const int bh  = blockIdx.y;           // 0..255
    const int q0  = blockIdx.x * BQ;

    const float* __restrict__ Qg = g_q + (size_t)bh * NN * HDIM;
    const float* __restrict__ Kg = g_k + (size_t)bh * NN * HDIM;
    const float* __restrict__ Vg = g_v + (size_t)bh * NN * HDIM;

    // load Q tile (zeros beyond N)
    for (int i = tid; i < BQ * 16; i += 128) {
        const int r  = i >> 4;
        const int d4 = (i & 15) * 4;
        float4 val = make_float4(0.f, 0.f, 0.f, 0.f);
        if (q0 + r < NN)
            val = *reinterpret_cast<const float4*>(Qg + (size_t)(q0 + r) * HDIM + d4);
        *reinterpret_cast<float4*>(&Qs[r][d4]) = val;
    }

    const int r    = tid >> 1;        // 0..63 q row
    const int half = tid & 1;
    const int j0   = half * 16;       // score cols owned
    const int dof  = half * 32;       // output dims owned

    float m_i = -INFINITY, l_i = 0.f;
    float acc[32];
#pragma unroll
    for (int dd = 0; dd < 32; dd++) acc[dd] = 0.f;

    const float scale = 0.125f;       // HD^-0.5
    const int nkt = (NN + BKT - 1) / BKT;   // 33

    for (int t = 0; t < nkt; t++) {
        const int k0 = t * BKT;
        __syncthreads();   // protect Ks/Vs/Ss from previous iteration readers
        for (int i = tid; i < BKT * 16; i += 128) {
            const int jr = i >> 4;
            const int d4 = (i & 15) * 4;
            float4 kv = make_float4(0.f, 0.f, 0.f, 0.f);
            float4 vv = make_float4(0.f, 0.f, 0.f, 0.f);
            if (k0 + jr < NN) {
                kv = *reinterpret_cast<const float4*>(Kg + (size_t)(k0 + jr) * HDIM + d4);
                vv = *reinterpret_cast<const float4*>(Vg + (size_t)(k0 + jr) * HDIM + d4);
            }
            *reinterpret_cast<float4*>(&Ks[jr][d4]) = kv;
            *reinterpret_cast<float4*>(&Vs[jr][d4]) = vv;
        }
        __syncthreads();

        // S = Q K^T for my 16 columns
        float s[16];
#pragma unroll
        for (int jj = 0; jj < 16; jj++) s[jj] = 0.f;
#pragma unroll
        for (int d4 = 0; d4 < HDIM; d4 += 4) {
            const float4 qv = *reinterpret_cast<const float4*>(&Qs[r][d4]);
#pragma unroll
            for (int jj = 0; jj < 16; jj++) {
                const float4 kv = *reinterpret_cast<const float4*>(&Ks[j0 + jj][d4]);
                s[jj] += qv.x * kv.x + qv.y * kv.y + qv.z * kv.z + qv.w * kv.w;
            }
        }
#pragma unroll
        for (int jj = 0; jj < 16; jj++) {
            const int gk = k0 + j0 + jj;
            Ss[r][j0 + jj] = (gk < NN) ? s[jj] * scale : -INFINITY;
        }
        __syncthreads();

        // online softmax over the full 32-wide row (pair threads redundantly)
        float mnew = m_i;
#pragma unroll
        for (int j = 0; j < BKT; j++) mnew = fmaxf(mnew, Ss[r][j]);
        const float alpha = __expf(m_i - mnew);
        float p[BKT];
        float lsum = 0.f;
#pragma unroll
        for (int j = 0; j < BKT; j++) {
            p[j] = __expf(Ss[r][j] - mnew);
            lsum += p[j];
        }
        l_i = l_i * alpha + lsum;
        m_i = mnew;

#pragma unroll
        for (int dd = 0; dd < 32; dd++) acc[dd] *= alpha;
#pragma unroll
        for (int j = 0; j < BKT; j++) {
            const float pj = p[j];
#pragma unroll
            for (int dd = 0; dd < 32; dd += 4) {
                const float4 vv = *reinterpret_cast<const float4*>(&Vs[j][dof + dd]);
                acc[dd + 0] = fmaf(pj, vv.x, acc[dd + 0]);
                acc[dd + 1] = fmaf(pj, vv.y, acc[dd + 1]);
                acc[dd + 2] = fmaf(pj, vv.z, acc[dd + 2]);
                acc[dd + 3] = fmaf(pj, vv.w, acc[dd + 3]);
            }
        }
    }

    const int qn = q0 + r;
    if (qn < NN) {
        const int b = bh / HH;
        const int h = bh % HH;
        const float inv = 1.f / l_i;
        const size_t base = ((size_t)(b * NN + qn)) * DD + h * HDIM + dof;
#pragma unroll
        for (int dd = 0; dd < 32; dd += 4) {
            float4 o;
            o.x = acc[dd + 0] * inv; o.y = acc[dd + 1] * inv;
            o.z = acc[dd + 2] * inv; o.w = acc[dd + 3] * inv;
            *reinterpret_cast<float4*>(ctx + base + dd) = o;   // 16B aligned: dof,dd mult of 4? base*4 mult of 16 yes
        }
    }
}

// ---------------- launch ----------------
extern "C" void kernel_launch(void* const* d_in, const int* in_sizes, int n_in,
                              void* d_out, int out_size)
{
    const float* hs  = (const float*)d_in[0];
    const float* sn  = (const float*)d_in[1];
    const float* cs  = (const float*)d_in[2];
    const float* Wq  = (const float*)d_in[3];
    const float* bq  = (const float*)d_in[4];
    const float* Wk  = (const float*)d_in[5];
    const float* bk  = (const float*)d_in[6];
    const float* Wv  = (const float*)d_in[7];
    const float* bv  = (const float*)d_in[8];
    const float* Wo  = (const float*)d_in[9];
    const float* bo  = (const float*)d_in[10];
    float* out = (float*)d_out;

    float *q, *k, *v, *ctx;
    cudaGetSymbolAddress((void**)&q,   g_q);
    cudaGetSymbolAddress((void**)&k,   g_k);
    cudaGetSymbolAddress((void**)&v,   g_v);
    cudaGetSymbolAddress((void**)&ctx, g_ctx);

    const dim3 ggrid(DD / 128, (MT + 127) / 128);   // 8 x 129
    gemm_kernel<1><<<ggrid, 256>>>(hs, Wq, bq, q);
    gemm_kernel<1><<<ggrid, 256>>>(hs, Wk, bk, k);
    gemm_kernel<1><<<ggrid, 256>>>(hs, Wv, bv, v);

    const int rope_threads = BB * HH * NP * 32;
    rope_kernel<<<(rope_threads + 255) / 256, 256>>>(sn, cs);

    const dim3 agrid((NN + BQ - 1) / BQ, BB * HH);  // 17 x 256
    attn_kernel<<<agrid, 128>>>(ctx);

    gemm_kernel<0><<<ggrid, 256>>>(ctx, Wo, bo, out);
}

// round 6
// speedup vs baseline: 1.3694x; 1.3694x over previous
#include <cuda_runtime.h>
#include <math.h>
#include <stdint.h>

#define BB 16
#define NN 1029
#define HH 16
#define HDIM 64
#define DD 1024
#define MT (BB*NN)          // 16464 rows
#define NP 1024             // rope table length
#define PREFIX (NN-NP)      // 5

// ---------------- scratch (no allocations allowed) ----------------
__device__ float g_q[(size_t)BB*HH*NN*HDIM];
__device__ float g_k[(size_t)BB*HH*NN*HDIM];
__device__ float g_v[(size_t)BB*HH*NN*HDIM];
__device__ float g_ctx[(size_t)BB*NN*DD];

// ---------------- helpers ----------------
__device__ __forceinline__ uint32_t f2tf(float x) {
    uint32_t u;
    asm("cvt.rna.tf32.f32 %0, %1;" : "=r"(u) : "f"(x));
    return u;
}

__device__ __forceinline__ void mma_tf32(float* d, const uint32_t* a, const uint32_t* b) {
    asm volatile(
        "mma.sync.aligned.m16n8k8.row.col.f32.tf32.tf32.f32 "
        "{%0,%1,%2,%3},{%4,%5,%6,%7},{%8,%9},{%0,%1,%2,%3};\n"
        : "+f"(d[0]), "+f"(d[1]), "+f"(d[2]), "+f"(d[3])
        : "r"(a[0]), "r"(a[1]), "r"(a[2]), "r"(a[3]), "r"(b[0]), "r"(b[1]));
}

// ---------------- tf32 tensor-core GEMM ----------------
// Y[m,n] = sum_k X[m,k]*W[n,k] + bias[n]
// MODE 0: row-major (M x D) output; MODE 1: (B,H,N,HD) head layout
// CTA tile 128x128, BK=16. 8 warps, each 64x32 (2x4 warp grid).
template<int MODE>
__global__ __launch_bounds__(256, 2)
void gemm_tf32_kernel(const float* __restrict__ X, const float* __restrict__ W,
                      const float* __restrict__ bias, float* __restrict__ Y)
{
    // k-major smem with +4k skew on the m/n index -> conflict-free fragment LDS
    __shared__ __align__(16) float As[16 * 128];
    __shared__ __align__(16) float Bs[16 * 128];

    const int tid  = threadIdx.x;
    const int lane = tid & 31;
    const int warp = tid >> 5;
    const int q    = lane & 3;          // threadID_in_group
    const int grp  = lane >> 2;         // groupID
    const int wm   = (warp >> 2) * 64;  // warp m offset (0 or 64)
    const int wn   = (warp & 3) * 32;   // warp n offset (0,32,64,96)

    const int bm = blockIdx.y * 128;
    const int bn = blockIdx.x * 128;

    float acc[4][4][4];
#pragma unroll
    for (int mi = 0; mi < 4; mi++)
#pragma unroll
        for (int ni = 0; ni < 4; ni++)
#pragma unroll
            for (int c = 0; c < 4; c++) acc[mi][ni][c] = 0.f;

    // global loader mapping: idx in [0,512): row = idx>>2, k-chunk = (idx&3)*4
    const int lr0 = tid >> 2;            // rows 0..63   (i=0)
    const int lr1 = (tid + 256) >> 2;    // rows 64..127 (i=1)
    const int lk4 = (tid & 3) << 2;      // 0,4,8,12

    float4 ra[2], rb[2];

    auto load_tiles = [&](int k0) {
        const int rows[2] = { lr0, lr1 };
#pragma unroll
        for (int i = 0; i < 2; i++) {
            const int gm = bm + rows[i];
            ra[i] = (gm < MT)
                ? *reinterpret_cast<const float4*>(X + (size_t)gm * DD + k0 + lk4)
                : make_float4(0.f, 0.f, 0.f, 0.f);
            rb[i] = *reinterpret_cast<const float4*>(W + (size_t)(bn + rows[i]) * DD + k0 + lk4);
        }
    };

    auto store_tiles = [&]() {
        const int rows[2] = { lr0, lr1 };
#pragma unroll
        for (int i = 0; i < 2; i++) {
            const float av[4] = { ra[i].x, ra[i].y, ra[i].z, ra[i].w };
            const float bv[4] = { rb[i].x, rb[i].y, rb[i].z, rb[i].w };
#pragma unroll
            for (int j = 0; j < 4; j++) {
                const int kr = lk4 + j;
                const int sk = (rows[i] + 4 * kr) & 127;   // skewed m/n index
                As[kr * 128 + sk] = __uint_as_float(f2tf(av[j]));
                Bs[kr * 128 + sk] = __uint_as_float(f2tf(bv[j]));
            }
        }
    };

    load_tiles(0);
    store_tiles();
    __syncthreads();

    const uint32_t* A32 = reinterpret_cast<const uint32_t*>(As);
    const uint32_t* B32 = reinterpret_cast<const uint32_t*>(Bs);

    for (int k0 = 16; k0 <= DD; k0 += 16) {
        const bool more = (k0 < DD);
        if (more) load_tiles(k0);

#pragma unroll
        for (int ks = 0; ks < 16; ks += 8) {
            const int kr0 = ks + q;
            const int kr1 = ks + q + 4;
            uint32_t a[4][4], b[4][2];
#pragma unroll
            for (int mi = 0; mi < 4; mi++) {
                const int m = wm + mi * 16 + grp;
                a[mi][0] = A32[kr0 * 128 + ((m     + 4 * kr0) & 127)];
                a[mi][1] = A32[kr0 * 128 + ((m + 8 + 4 * kr0) & 127)];
                a[mi][2] = A32[kr1 * 128 + ((m     + 4 * kr1) & 127)];
                a[mi][3] = A32[kr1 * 128 + ((m + 8 + 4 * kr1) & 127)];
            }
#pragma unroll
            for (int ni = 0; ni < 4; ni++) {
                const int n = wn + ni * 8 + grp;
                b[ni][0] = B32[kr0 * 128 + ((n + 4 * kr0) & 127)];
                b[ni][1] = B32[kr1 * 128 + ((n + 4 * kr1) & 127)];
            }
#pragma unroll
            for (int mi = 0; mi < 4; mi++)
#pragma unroll
                for (int ni = 0; ni < 4; ni++)
                    mma_tf32(acc[mi][ni], a[mi], b[ni]);
        }

        if (more) {
            __syncthreads();
            store_tiles();
            __syncthreads();
        }
    }

    // epilogue: c0,c1 at (row, 2q),(row, 2q+1); c2,c3 at row+8
#pragma unroll
    for (int mi = 0; mi < 4; mi++) {
#pragma unroll
        for (int half = 0; half < 2; half++) {
            const int gm = bm + wm + mi * 16 + grp + half * 8;
            if (gm >= MT) continue;
            const int bb = gm / NN;
            const int nn = gm - bb * NN;
#pragma unroll
            for (int ni = 0; ni < 4; ni++) {
                const int gn = bn + wn + ni * 8 + 2 * q;
                float2 o;
                o.x = acc[mi][ni][half * 2 + 0] + bias[gn];
                o.y = acc[mi][ni][half * 2 + 1] + bias[gn + 1];
                if (MODE == 0) {
                    *reinterpret_cast<float2*>(Y + (size_t)gm * DD + gn) = o;
                } else {
                    const int h  = gn >> 6;
                    const int hd = gn & 63;
                    *reinterpret_cast<float2*>(
                        Y + (((size_t)(bb * HH + h)) * NN + nn) * HDIM + hd) = o;
                }
            }
        }
    }
}

// ---------------- RoPE on q and k (in-place, rows n >= PREFIX) ----------------
__global__ __launch_bounds__(256)
void rope_kernel(const float* __restrict__ sinp, const float* __restrict__ cosp)
{
    const int idx = blockIdx.x * blockDim.x + threadIdx.x;
    const int total = BB * HH * NP * 32;
    if (idx >= total) return;
    const int d  = idx & 31;
    const int r  = idx >> 5;
    const int n  = r % NP;
    const int bh = r / NP;
    const size_t base = ((size_t)bh * NN + (n + PREFIX)) * HDIM;

    const float c1 = cosp[n * HDIM + d];
    const float c2 = cosp[n * HDIM + d + 32];
    const float s1 = sinp[n * HDIM + d];
    const float s2 = sinp[n * HDIM + d + 32];

    const float q1 = g_q[base + d], q2 = g_q[base + d + 32];
    g_q[base + d]      = q1 * c1 - q2 * s1;
    g_q[base + d + 32] = q2 * c2 + q1 * s2;

    const float k1 = g_k[base + d], k2 = g_k[base + d + 32];
    g_k[base + d]      = k1 * c1 - k2 * s1;
    g_k[base + d + 32] = k2 * c2 + k1 * s2;
}

// ---------------- Flash attention: per (b,h), 64 q-rows per CTA ----------------
#define BQ 64
#define BKT 32

__global__ __launch_bounds__(128)
void attn_kernel(float* __restrict__ ctx)
{
    __shared__ __align__(16) float Qs[BQ][HDIM + 4];
    __shared__ __align__(16) float Ks[BKT][HDIM];
    __shared__ __align__(16) float Vs[BKT][HDIM];
    __shared__ float Ss[BQ][BKT + 1];

    const int tid = threadIdx.x;          // 128
    const int bh  = blockIdx.y;           // 0..255
    const int q0  = blockIdx.x * BQ;

    const float* __restrict__ Qg = g_q + (size_t)bh * NN * HDIM;
    const float* __restrict__ Kg = g_k + (size_t)bh * NN * HDIM;
    const float* __restrict__ Vg = g_v + (size_t)bh * NN * HDIM;

    for (int i = tid; i < BQ * 16; i += 128) {
        const int r  = i >> 4;
        const int d4 = (i & 15) * 4;
        float4 val = make_float4(0.f, 0.f, 0.f, 0.f);
        if (q0 + r < NN)
            val = *reinterpret_cast<const float4*>(Qg + (size_t)(q0 + r) * HDIM + d4);
        *reinterpret_cast<float4*>(&Qs[r][d4]) = val;
    }

    const int r    = tid >> 1;        // 0..63 q row
    const int half = tid & 1;
    const int j0   = half * 16;       // score cols owned
    const int dof  = half * 32;       // output dims owned

    float m_i = -INFINITY, l_i = 0.f;
    float acc[32];
#pragma unroll
    for (int dd = 0; dd < 32; dd++) acc[dd] = 0.f;

    const float scale = 0.125f;       // HD^-0.5
    const int nkt = (NN + BKT - 1) / BKT;   // 33

    for (int t = 0; t < nkt; t++) {
        const int k0 = t * BKT;
        __syncthreads();
        for (int i = tid; i < BKT * 16; i += 128) {
            const int jr = i >> 4;
            const int d4 = (i & 15) * 4;
            float4 kv = make_float4(0.f, 0.f, 0.f, 0.f);
            float4 vv = make_float4(0.f, 0.f, 0.f, 0.f);
            if (k0 + jr < NN) {
                kv = *reinterpret_cast<const float4*>(Kg + (size_t)(k0 + jr) * HDIM + d4);
                vv = *reinterpret_cast<const float4*>(Vg + (size_t)(k0 + jr) * HDIM + d4);
            }
            *reinterpret_cast<float4*>(&Ks[jr][d4]) = kv;
            *reinterpret_cast<float4*>(&Vs[jr][d4]) = vv;
        }
        __syncthreads();

        float s[16];
#pragma unroll
        for (int jj = 0; jj < 16; jj++) s[jj] = 0.f;
#pragma unroll
        for (int d4 = 0; d4 < HDIM; d4 += 4) {
            const float4 qv = *reinterpret_cast<const float4*>(&Qs[r][d4]);
#pragma unroll
            for (int jj = 0; jj < 16; jj++) {
                const float4 kv = *reinterpret_cast<const float4*>(&Ks[j0 + jj][d4]);
                s[jj] += qv.x * kv.x + qv.y * kv.y + qv.z * kv.z + qv.w * kv.w;
            }
        }
#pragma unroll
        for (int jj = 0; jj < 16; jj++) {
            const int gk = k0 + j0 + jj;
            Ss[r][j0 + jj] = (gk < NN) ? s[jj] * scale : -INFINITY;
        }
        __syncthreads();

        float mnew = m_i;
#pragma unroll
        for (int j = 0; j < BKT; j++) mnew = fmaxf(mnew, Ss[r][j]);
        const float alpha = __expf(m_i - mnew);
        float p[BKT];
        float lsum = 0.f;
#pragma unroll
        for (int j = 0; j < BKT; j++) {
            p[j] = __expf(Ss[r][j] - mnew);
            lsum += p[j];
        }
        l_i = l_i * alpha + lsum;
        m_i = mnew;

#pragma unroll
        for (int dd = 0; dd < 32; dd++) acc[dd] *= alpha;
#pragma unroll
        for (int j = 0; j < BKT; j++) {
            const float pj = p[j];
#pragma unroll
            for (int dd = 0; dd < 32; dd += 4) {
                const float4 vv = *reinterpret_cast<const float4*>(&Vs[j][dof + dd]);
                acc[dd + 0] = fmaf(pj, vv.x, acc[dd + 0]);
                acc[dd + 1] = fmaf(pj, vv.y, acc[dd + 1]);
                acc[dd + 2] = fmaf(pj, vv.z, acc[dd + 2]);
                acc[dd + 3] = fmaf(pj, vv.w, acc[dd + 3]);
            }
        }
    }

    const int qn = q0 + r;
    if (qn < NN) {
        const int b = bh / HH;
        const int h = bh % HH;
        const float inv = 1.f / l_i;
        const size_t base = ((size_t)(b * NN + qn)) * DD + h * HDIM + dof;
#pragma unroll
        for (int dd = 0; dd < 32; dd += 4) {
            float4 o;
            o.x = acc[dd + 0] * inv; o.y = acc[dd + 1] * inv;
            o.z = acc[dd + 2] * inv; o.w = acc[dd + 3] * inv;
            *reinterpret_cast<float4*>(ctx + base + dd) = o;
        }
    }
}

// ---------------- launch ----------------
extern "C" void kernel_launch(void* const* d_in, const int* in_sizes, int n_in,
                              void* d_out, int out_size)
{
    const float* hs  = (const float*)d_in[0];
    const float* sn  = (const float*)d_in[1];
    const float* cs  = (const float*)d_in[2];
    const float* Wq  = (const float*)d_in[3];
    const float* bq  = (const float*)d_in[4];
    const float* Wk  = (const float*)d_in[5];
    const float* bk  = (const float*)d_in[6];
    const float* Wv  = (const float*)d_in[7];
    const float* bv  = (const float*)d_in[8];
    const float* Wo  = (const float*)d_in[9];
    const float* bo  = (const float*)d_in[10];
    float* out = (float*)d_out;

    float *q, *k, *v, *ctx;
    cudaGetSymbolAddress((void**)&q,   g_q);
    cudaGetSymbolAddress((void**)&k,   g_k);
    cudaGetSymbolAddress((void**)&v,   g_v);
    cudaGetSymbolAddress((void**)&ctx, g_ctx);

    const dim3 ggrid(DD / 128, (MT + 127) / 128);   // 8 x 129
    gemm_tf32_kernel<1><<<ggrid, 256>>>(hs, Wq, bq, q);
    gemm_tf32_kernel<1><<<ggrid, 256>>>(hs, Wk, bk, k);
    gemm_tf32_kernel<1><<<ggrid, 256>>>(hs, Wv, bv, v);

    const int rope_threads = BB * HH * NP * 32;
    rope_kernel<<<(rope_threads + 255) / 256, 256>>>(sn, cs);

    const dim3 agrid((NN + BQ - 1) / BQ, BB * HH);  // 17 x 256
    attn_kernel<<<agrid, 128>>>(ctx);

    gemm_tf32_kernel<0><<<ggrid, 256>>>(ctx, Wo, bo, out);
}

// round 8
// speedup vs baseline: 3.3696x; 2.4606x over previous
#include <cuda_runtime.h>
#include <math.h>
#include <stdint.h>

#define BB 16
#define NN 1029
#define HH 16
#define HDIM 64
#define DD 1024
#define MT (BB*NN)          // 16464 rows
#define NP 1024             // rope table length
#define PREFIX (NN-NP)      // 5

// ---------------- scratch (no allocations allowed) ----------------
__device__ float g_q[(size_t)BB*HH*NN*HDIM];
__device__ float g_k[(size_t)BB*HH*NN*HDIM];
__device__ float g_v[(size_t)BB*HH*NN*HDIM];
__device__ float g_ctx[(size_t)BB*NN*DD];

// ---------------- helpers ----------------
__device__ __forceinline__ uint32_t f2tf(float x) {
    uint32_t u;
    asm("cvt.rna.tf32.f32 %0, %1;" : "=r"(u) : "f"(x));
    return u;
}

__device__ __forceinline__ void mma_tf32(float* d, const uint32_t* a, const uint32_t* b) {
    asm volatile(
        "mma.sync.aligned.m16n8k8.row.col.f32.tf32.tf32.f32 "
        "{%0,%1,%2,%3},{%4,%5,%6,%7},{%8,%9},{%0,%1,%2,%3};\n"
        : "+f"(d[0]), "+f"(d[1]), "+f"(d[2]), "+f"(d[3])
        : "r"(a[0]), "r"(a[1]), "r"(a[2]), "r"(a[3]), "r"(b[0]), "r"(b[1]));
}

// ---------------- tf32 tensor-core GEMM ----------------
// Y[m,n] = sum_k X[m,k]*W[n,k] + bias[n]
// MODE 0: plain row-major (M x D) output; MODE 1: (B,H,N,HD) head layout
template<int MODE>
__global__ __launch_bounds__(256, 2)
void gemm_tf32_kernel(const float* __restrict__ X, const float* __restrict__ W,
                      const float* __restrict__ bias, float* __restrict__ Y)
{
    __shared__ __align__(16) float As[16 * 128];
    __shared__ __align__(16) float Bs[16 * 128];

    const int tid  = threadIdx.x;
    const int lane = tid & 31;
    const int warp = tid >> 5;
    const int q    = lane & 3;
    const int grp  = lane >> 2;
    const int wm   = (warp >> 2) * 64;
    const int wn   = (warp & 3) * 32;

    const int bm = blockIdx.y * 128;
    const int bn = blockIdx.x * 128;

    float acc[4][4][4];
#pragma unroll
    for (int mi = 0; mi < 4; mi++)
#pragma unroll
        for (int ni = 0; ni < 4; ni++)
#pragma unroll
            for (int c = 0; c < 4; c++) acc[mi][ni][c] = 0.f;

    const int lr0 = tid >> 2;
    const int lr1 = (tid + 256) >> 2;
    const int lk4 = (tid & 3) << 2;

    float4 ra[2], rb[2];

    auto load_tiles = [&](int k0) {
        const int rows[2] = { lr0, lr1 };
#pragma unroll
        for (int i = 0; i < 2; i++) {
            const int gm = bm + rows[i];
            ra[i] = (gm < MT)
                ? *reinterpret_cast<const float4*>(X + (size_t)gm * DD + k0 + lk4)
                : make_float4(0.f, 0.f, 0.f, 0.f);
            rb[i] = *reinterpret_cast<const float4*>(W + (size_t)(bn + rows[i]) * DD + k0 + lk4);
        }
    };

    auto store_tiles = [&]() {
        const int rows[2] = { lr0, lr1 };
#pragma unroll
        for (int i = 0; i < 2; i++) {
            const float av[4] = { ra[i].x, ra[i].y, ra[i].z, ra[i].w };
            const float bv[4] = { rb[i].x, rb[i].y, rb[i].z, rb[i].w };
#pragma unroll
            for (int j = 0; j < 4; j++) {
                const int kr = lk4 + j;
                const int sk = (rows[i] + 4 * kr) & 127;
                As[kr * 128 + sk] = __uint_as_float(f2tf(av[j]));
                Bs[kr * 128 + sk] = __uint_as_float(f2tf(bv[j]));
            }
        }
    };

    load_tiles(0);
    store_tiles();
    __syncthreads();

    const uint32_t* A32 = reinterpret_cast<const uint32_t*>(As);
    const uint32_t* B32 = reinterpret_cast<const uint32_t*>(Bs);

    for (int k0 = 16; k0 <= DD; k0 += 16) {
        const bool more = (k0 < DD);
        if (more) load_tiles(k0);

#pragma unroll
        for (int ks = 0; ks < 16; ks += 8) {
            const int kr0 = ks + q;
            const int kr1 = ks + q + 4;
            uint32_t a[4][4], b[4][2];
#pragma unroll
            for (int mi = 0; mi < 4; mi++) {
                const int m = wm + mi * 16 + grp;
                a[mi][0] = A32[kr0 * 128 + ((m     + 4 * kr0) & 127)];
                a[mi][1] = A32[kr0 * 128 + ((m + 8 + 4 * kr0) & 127)];
                a[mi][2] = A32[kr1 * 128 + ((m     + 4 * kr1) & 127)];
                a[mi][3] = A32[kr1 * 128 + ((m + 8 + 4 * kr1) & 127)];
            }
#pragma unroll
            for (int ni = 0; ni < 4; ni++) {
                const int n = wn + ni * 8 + grp;
                b[ni][0] = B32[kr0 * 128 + ((n + 4 * kr0) & 127)];
                b[ni][1] = B32[kr1 * 128 + ((n + 4 * kr1) & 127)];
            }
#pragma unroll
            for (int mi = 0; mi < 4; mi++)
#pragma unroll
                for (int ni = 0; ni < 4; ni++)
                    mma_tf32(acc[mi][ni], a[mi], b[ni]);
        }

        if (more) {
            __syncthreads();
            store_tiles();
            __syncthreads();
        }
    }

#pragma unroll
    for (int mi = 0; mi < 4; mi++) {
#pragma unroll
        for (int half = 0; half < 2; half++) {
            const int gm = bm + wm + mi * 16 + grp + half * 8;
            if (gm >= MT) continue;
            const int bb = gm / NN;
            const int nn = gm - bb * NN;
#pragma unroll
            for (int ni = 0; ni < 4; ni++) {
                const int gn = bn + wn + ni * 8 + 2 * q;
                float2 o;
                o.x = acc[mi][ni][half * 2 + 0] + bias[gn];
                o.y = acc[mi][ni][half * 2 + 1] + bias[gn + 1];
                if (MODE == 0) {
                    *reinterpret_cast<float2*>(Y + (size_t)gm * DD + gn) = o;
                } else {
                    const int h  = gn >> 6;
                    const int hd = gn & 63;
                    *reinterpret_cast<float2*>(
                        Y + (((size_t)(bb * HH + h)) * NN + nn) * HDIM + hd) = o;
                }
            }
        }
    }
}

// ---------------- RoPE on q and k (in-place, rows n >= PREFIX) ----------------
__global__ __launch_bounds__(256)
void rope_kernel(const float* __restrict__ sinp, const float* __restrict__ cosp)
{
    const int idx = blockIdx.x * blockDim.x + threadIdx.x;
    const int total = BB * HH * NP * 32;
    if (idx >= total) return;
    const int d  = idx & 31;
    const int r  = idx >> 5;
    const int n  = r % NP;
    const int bh = r / NP;
    const size_t base = ((size_t)bh * NN + (n + PREFIX)) * HDIM;

    const float c1 = cosp[n * HDIM + d];
    const float c2 = cosp[n * HDIM + d + 32];
    const float s1 = sinp[n * HDIM + d];
    const float s2 = sinp[n * HDIM + d + 32];

    const float q1 = g_q[base + d], q2 = g_q[base + d + 32];
    g_q[base + d]      = q1 * c1 - q2 * s1;
    g_q[base + d + 32] = q2 * c2 + q1 * s2;

    const float k1 = g_k[base + d], k2 = g_k[base + d + 32];
    g_k[base + d]      = k1 * c1 - k2 * s1;
    g_k[base + d + 32] = k2 * c2 + k1 * s2;
}

// ---------------- tensor-core flash attention ----------------
// BQ=128 q-rows per CTA, BKT=64 k-rows per tile, 8 warps each owning a
// 16-row m-stripe. tf32 mma for QK^T and PV; online softmax in accumulator
// layout; K-tile smem region reused for the P tile.
#define AQ 128
#define AKT 64
#define ASTR 68                       // smem row stride (floats)
#define ATTN_SMEM ((2*AQ*ASTR + HDIM*ASTR) * 4)   // 87040 bytes

__global__ __launch_bounds__(256, 2)
void attn_tc_kernel(float* __restrict__ ctx)
{
    extern __shared__ float sm[];
    float* Qs = sm;                   // [AQ][ASTR]   tf32 Q
    float* PK = sm + AQ * ASTR;       // Ks [AKT][ASTR] then Ps [AQ][ASTR]
    float* Vt = sm + 2 * AQ * ASTR;   // [HDIM][ASTR] tf32 V transposed [d][kt]

    const int tid  = threadIdx.x;
    const int lane = tid & 31;
    const int warp = tid >> 5;
    const int q    = lane & 3;
    const int grp  = lane >> 2;
    const int bh   = blockIdx.y;
    const int q0   = blockIdx.x * AQ;

    const float* __restrict__ Qg = g_q + (size_t)bh * NN * HDIM;
    const float* __restrict__ Kg = g_k + (size_t)bh * NN * HDIM;
    const float* __restrict__ Vg = g_v + (size_t)bh * NN * HDIM;

    // load Q tile (tf32), coalesced, zero-padded
#pragma unroll
    for (int it = 0; it < 8; it++) {
        const int i  = tid + it * 256;
        const int r  = i >> 4;
        const int d4 = (i & 15) * 4;
        float4 v = make_float4(0.f, 0.f, 0.f, 0.f);
        if (q0 + r < NN)
            v = *reinterpret_cast<const float4*>(Qg + (size_t)(q0 + r) * HDIM + d4);
        uint4 u;
        u.x = f2tf(v.x); u.y = f2tf(v.y); u.z = f2tf(v.z); u.w = f2tf(v.w);
        *reinterpret_cast<uint4*>(Qs + r * ASTR + d4) = u;
    }

    float m0 = -INFINITY, m1 = -INFINITY, l0 = 0.f, l1 = 0.f;
    float acc_o[8][4];
#pragma unroll
    for (int nt = 0; nt < 8; nt++)
#pragma unroll
        for (int c = 0; c < 4; c++) acc_o[nt][c] = 0.f;

    const int row_s = warp * 16 + grp;           // this thread's m-row in smem
    const float scale = 0.125f;                  // HD^-0.5
    const int nkt = (NN + AKT - 1) / AKT;        // 17

    for (int t = 0; t < nkt; t++) {
        const int k0 = t * AKT;
        __syncthreads();   // prior PV reads of PK/Vt done

        // K tile -> PK (row-major [kt][d], coalesced, conflict-free STS.128)
#pragma unroll
        for (int it = 0; it < 4; it++) {
            const int i  = tid + it * 256;
            const int kt = i >> 4;
            const int d4 = (i & 15) * 4;
            float4 v = make_float4(0.f, 0.f, 0.f, 0.f);
            if (k0 + kt < NN)
                v = *reinterpret_cast<const float4*>(Kg + (size_t)(k0 + kt) * HDIM + d4);
            uint4 u;
            u.x = f2tf(v.x); u.y = f2tf(v.y); u.z = f2tf(v.z); u.w = f2tf(v.w);
            *reinterpret_cast<uint4*>(PK + kt * ASTR + d4) = u;
        }
        // V tile -> Vt transposed [d][kt] (conflict-free STS.32: bank = kt)
#pragma unroll
        for (int it = 0; it < 4; it++) {
            const int i  = tid + it * 256;
            const int kt = i & 63;
            const int d4 = (i >> 6) * 4;
            float4 v = make_float4(0.f, 0.f, 0.f, 0.f);
            if (k0 + kt < NN)
                v = *reinterpret_cast<const float4*>(Vg + (size_t)(k0 + kt) * HDIM + d4);
            Vt[(d4 + 0) * ASTR + kt] = __uint_as_float(f2tf(v.x));
            Vt[(d4 + 1) * ASTR + kt] = __uint_as_float(f2tf(v.y));
            Vt[(d4 + 2) * ASTR + kt] = __uint_as_float(f2tf(v.z));
            Vt[(d4 + 3) * ASTR + kt] = __uint_as_float(f2tf(v.w));
        }
        __syncthreads();

        // ---- S = Q K^T (raw, scaled later) ----
        float acc_s[8][4];
#pragma unroll
        for (int nt = 0; nt < 8; nt++)
#pragma unroll
            for (int c = 0; c < 4; c++) acc_s[nt][c] = 0.f;

        const uint32_t* Q32 = reinterpret_cast<const uint32_t*>(Qs);
        const uint32_t* K32 = reinterpret_cast<const uint32_t*>(PK);
#pragma unroll
        for (int ks = 0; ks < 8; ks++) {
            const int kk = ks * 8;
            uint32_t a[4];
            a[0] = Q32[(row_s    ) * ASTR + kk + q    ];
            a[1] = Q32[(row_s + 8) * ASTR + kk + q    ];
            a[2] = Q32[(row_s    ) * ASTR + kk + q + 4];
            a[3] = Q32[(row_s + 8) * ASTR + kk + q + 4];
#pragma unroll
            for (int nt = 0; nt < 8; nt++) {
                uint32_t b[2];
                b[0] = K32[(nt * 8 + grp) * ASTR + kk + q    ];
                b[1] = K32[(nt * 8 + grp) * ASTR + kk + q + 4];
                mma_tf32(acc_s[nt], a, b);
            }
        }

        // ---- online softmax ----
        float r0m = -INFINITY, r1m = -INFINITY;
#pragma unroll
        for (int nt = 0; nt < 8; nt++) {
            const int c = k0 + nt * 8 + 2 * q;
            const float s0 = (c     < NN) ? acc_s[nt][0] * scale : -INFINITY;
            const float s1 = (c + 1 < NN) ? acc_s[nt][1] * scale : -INFINITY;
            const float s2 = (c     < NN) ? acc_s[nt][2] * scale : -INFINITY;
            const float s3 = (c + 1 < NN) ? acc_s[nt][3] * scale : -INFINITY;
            acc_s[nt][0] = s0; acc_s[nt][1] = s1;
            acc_s[nt][2] = s2; acc_s[nt][3] = s3;
            r0m = fmaxf(r0m, fmaxf(s0, s1));
            r1m = fmaxf(r1m, fmaxf(s2, s3));
        }
        r0m = fmaxf(r0m, __shfl_xor_sync(0xffffffffu, r0m, 1));
        r0m = fmaxf(r0m, __shfl_xor_sync(0xffffffffu, r0m, 2));
        r1m = fmaxf(r1m, __shfl_xor_sync(0xffffffffu, r1m, 1));
        r1m = fmaxf(r1m, __shfl_xor_sync(0xffffffffu, r1m, 2));

        const float m0n = fmaxf(m0, r0m);
        const float m1n = fmaxf(m1, r1m);
        const float a0  = __expf(m0 - m0n);
        const float a1  = __expf(m1 - m1n);

        float sum0 = 0.f, sum1 = 0.f;
#pragma unroll
        for (int nt = 0; nt < 8; nt++) {
            const float p0 = __expf(acc_s[nt][0] - m0n);
            const float p1 = __expf(acc_s[nt][1] - m0n);
            const float p2 = __expf(acc_s[nt][2] - m1n);
            const float p3 = __expf(acc_s[nt][3] - m1n);
            acc_s[nt][0] = p0; acc_s[nt][1] = p1;
            acc_s[nt][2] = p2; acc_s[nt][3] = p3;
            sum0 += p0 + p1; sum1 += p2 + p3;
        }
        sum0 += __shfl_xor_sync(0xffffffffu, sum0, 1);
        sum0 += __shfl_xor_sync(0xffffffffu, sum0, 2);
        sum1 += __shfl_xor_sync(0xffffffffu, sum1, 1);
        sum1 += __shfl_xor_sync(0xffffffffu, sum1, 2);

        l0 = l0 * a0 + sum0;
        l1 = l1 * a1 + sum1;
        m0 = m0n; m1 = m1n;

#pragma unroll
        for (int nt = 0; nt < 8; nt++) {
            acc_o[nt][0] *= a0; acc_o[nt][1] *= a0;
            acc_o[nt][2] *= a1; acc_o[nt][3] *= a1;
        }

        __syncthreads();   // all warps finished reading K tile
        // write P (tf32) into the K region
#pragma unroll
        for (int nt = 0; nt < 8; nt++) {
            float2 p01, p23;
            p01.x = __uint_as_float(f2tf(acc_s[nt][0]));
            p01.y = __uint_as_float(f2tf(acc_s[nt][1]));
            p23.x = __uint_as_float(f2tf(acc_s[nt][2]));
            p23.y = __uint_as_float(f2tf(acc_s[nt][3]));
            *reinterpret_cast<float2*>(PK + (row_s    ) * ASTR + nt * 8 + 2 * q) = p01;
            *reinterpret_cast<float2*>(PK + (row_s + 8) * ASTR + nt * 8 + 2 * q) = p23;
        }
        __syncthreads();

        // ---- O += P V ----
        const uint32_t* P32 = reinterpret_cast<const uint32_t*>(PK);
        const uint32_t* V32 = reinterpret_cast<const uint32_t*>(Vt);
#pragma unroll
        for (int ks = 0; ks < 8; ks++) {
            const int kk = ks * 8;
            uint32_t a[4];
            a[0] = P32[(row_s    ) * ASTR + kk + q    ];
            a[1] = P32[(row_s + 8) * ASTR + kk + q    ];
            a[2] = P32[(row_s    ) * ASTR + kk + q + 4];
            a[3] = P32[(row_s + 8) * ASTR + kk + q + 4];
#pragma unroll
            for (int nt = 0; nt < 8; nt++) {
                uint32_t b[2];
                b[0] = V32[(nt * 8 + grp) * ASTR + kk + q    ];
                b[1] = V32[(nt * 8 + grp) * ASTR + kk + q + 4];
                mma_tf32(acc_o[nt], a, b);
            }
        }
    }

    // ---- epilogue: O / l -> ctx (B, N, D) at head offset ----
    const int b = bh / HH;
    const int h = bh % HH;
    const float inv0 = 1.f / l0;
    const float inv1 = 1.f / l1;
    const int r0g = q0 + warp * 16 + grp;
    const int r1g = r0g + 8;
#pragma unroll
    for (int nt = 0; nt < 8; nt++) {
        const int d = h * HDIM + nt * 8 + 2 * q;
        if (r0g < NN) {
            float2 o; o.x = acc_o[nt][0] * inv0; o.y = acc_o[nt][1] * inv0;
            *reinterpret_cast<float2*>(ctx + ((size_t)(b * NN + r0g)) * DD + d) = o;
        }
        if (r1g < NN) {
            float2 o; o.x = acc_o[nt][2] * inv1; o.y = acc_o[nt][3] * inv1;
            *reinterpret_cast<float2*>(ctx + ((size_t)(b * NN + r1g)) * DD + d) = o;
        }
    }
}

// ---------------- launch ----------------
extern "C" void kernel_launch(void* const* d_in, const int* in_sizes, int n_in,
                              void* d_out, int out_size)
{
    const float* hs  = (const float*)d_in[0];
    const float* sn  = (const float*)d_in[1];
    const float* cs  = (const float*)d_in[2];
    const float* Wq  = (const float*)d_in[3];
    const float* bq  = (const float*)d_in[4];
    const float* Wk  = (const float*)d_in[5];
    const float* bk  = (const float*)d_in[6];
    const float* Wv  = (const float*)d_in[7];
    const float* bv  = (const float*)d_in[8];
    const float* Wo  = (const float*)d_in[9];
    const float* bo  = (const float*)d_in[10];
    float* out = (float*)d_out;

    float *q, *k, *v, *ctx;
    cudaGetSymbolAddress((void**)&q,   g_q);
    cudaGetSymbolAddress((void**)&k,   g_k);
    cudaGetSymbolAddress((void**)&v,   g_v);
    cudaGetSymbolAddress((void**)&ctx, g_ctx);

    cudaFuncSetAttribute(attn_tc_kernel,
                         cudaFuncAttributeMaxDynamicSharedMemorySize, ATTN_SMEM);

    const dim3 ggrid(DD / 128, (MT + 127) / 128);   // 8 x 129
    gemm_tf32_kernel<1><<<ggrid, 256>>>(hs, Wq, bq, q);
    gemm_tf32_kernel<1><<<ggrid, 256>>>(hs, Wk, bk, k);
    gemm_tf32_kernel<1><<<ggrid, 256>>>(hs, Wv, bv, v);

    const int rope_threads = BB * HH * NP * 32;
    rope_kernel<<<(rope_threads + 255) / 256, 256>>>(sn, cs);

    const dim3 agrid((NN + AQ - 1) / AQ, BB * HH);  // 9 x 256
    attn_tc_kernel<<<agrid, 256, ATTN_SMEM>>>(ctx);

    gemm_tf32_kernel<0><<<ggrid, 256>>>(ctx, Wo, bo, out);
}

// round 11
// speedup vs baseline: 5.8141x; 1.7255x over previous
#include <cuda_runtime.h>
#include <cuda_fp16.h>
#include <math.h>
#include <stdint.h>

#define BB 16
#define NN 1029
#define HH 16
#define HDIM 64
#define DD 1024
#define MT (BB*NN)          // 16464 rows
#define NP 1024             // rope table length
#define PREFIX (NN-NP)      // 5

// ---------------- scratch (no allocations allowed) ----------------
__device__ float g_q[(size_t)BB*HH*NN*HDIM];
__device__ float g_k[(size_t)BB*HH*NN*HDIM];
__device__ float g_v[(size_t)BB*HH*NN*HDIM];
__device__ float g_ctx[(size_t)BB*NN*DD];

// ---------------- helpers ----------------
__device__ __forceinline__ uint32_t fpack(float a, float b) {
    __half2 h = __floats2half2_rn(a, b);
    return *reinterpret_cast<uint32_t*>(&h);
}

__device__ __forceinline__ void mma_f16(float* d, const uint32_t* a, const uint32_t* b) {
    asm volatile(
        "mma.sync.aligned.m16n8k16.row.col.f32.f16.f16.f32 "
        "{%0,%1,%2,%3},{%4,%5,%6,%7},{%8,%9},{%0,%1,%2,%3};\n"
        : "+f"(d[0]), "+f"(d[1]), "+f"(d[2]), "+f"(d[3])
        : "r"(a[0]), "r"(a[1]), "r"(a[2]), "r"(a[3]), "r"(b[0]), "r"(b[1]));
}

// ---------------- fp16 tensor-core GEMM ----------------
// Y[m,n] = sum_k X[m,k]*W[n,k] + bias[n]
// MODE 0: row-major (M x D) output; MODE 1: (B,H,N,HD) head layout
// CTA tile 128x128, BK=16 (one m16n8k16 step/iter). 8 warps of 64x32.
// smem: [row][k] halves, row stride 24 halves (12 u32) -> fragment LDS
// bank = (12*grp + q) mod 32, a bijection over the warp: conflict-free.
#define GSTR32 12      // row stride in uint32 (24 halves)

template<int MODE>
__global__ __launch_bounds__(256, 2)
void gemm_f16_kernel(const float* __restrict__ X, const float* __restrict__ W,
                     const float* __restrict__ bias, float* __restrict__ Y)
{
    __shared__ __align__(16) uint32_t As[128 * GSTR32];
    __shared__ __align__(16) uint32_t Bs[128 * GSTR32];

    const int tid  = threadIdx.x;
    const int lane = tid & 31;
    const int warp = tid >> 5;
    const int q    = lane & 3;
    const int grp  = lane >> 2;
    const int wm   = (warp >> 2) * 64;
    const int wn   = (warp & 3) * 32;

    const int bm = blockIdx.y * 128;
    const int bn = blockIdx.x * 128;

    float acc[4][4][4];
#pragma unroll
    for (int mi = 0; mi < 4; mi++)
#pragma unroll
        for (int ni = 0; ni < 4; ni++)
#pragma unroll
            for (int c = 0; c < 4; c++) acc[mi][ni][c] = 0.f;

    // loader: 512 float4-chunks per tile pair -> 2 per thread per array
    const int lrow0 = tid >> 1;            // rows 0..127 (chunk set 0)
    const int lk0   = (tid & 1) * 8;       // halves 0 or 8
    // second chunk: same thread covers the other 8-half group of row lrow0? No:
    // use c = tid + 256: row = (tid+256)>>1 wraps -> cover via two its below.

    float4 ra[2], rb[2];

    auto load_tiles = [&](int k0) {
#pragma unroll
        for (int it = 0; it < 2; it++) {
            const int c   = tid + it * 256;
            const int row = c >> 2;              // 0..127
            const int kq4 = (c & 3) * 4;         // 0,4,8,12
            const int gm  = bm + row;
            ra[it] = (gm < MT)
                ? *reinterpret_cast<const float4*>(X + (size_t)gm * DD + k0 + kq4)
                : make_float4(0.f, 0.f, 0.f, 0.f);
            rb[it] = *reinterpret_cast<const float4*>(W + (size_t)(bn + row) * DD + k0 + kq4);
        }
    };

    auto store_tiles = [&]() {
#pragma unroll
        for (int it = 0; it < 2; it++) {
            const int c   = tid + it * 256;
            const int row = c >> 2;
            const int kq4 = (c & 3) * 4;
            const int idx = row * GSTR32 + (kq4 >> 1);   // even -> uint2 ok
            uint2 ua, ub;
            ua.x = fpack(ra[it].x, ra[it].y); ua.y = fpack(ra[it].z, ra[it].w);
            ub.x = fpack(rb[it].x, rb[it].y); ub.y = fpack(rb[it].z, rb[it].w);
            *reinterpret_cast<uint2*>(&As[idx]) = ua;
            *reinterpret_cast<uint2*>(&Bs[idx]) = ub;
        }
    };

    load_tiles(0);
    store_tiles();
    __syncthreads();

    for (int k0 = 16; k0 <= DD; k0 += 16) {
        const bool more = (k0 < DD);
        if (more) load_tiles(k0);

        uint32_t a[4][4], b[4][2];
#pragma unroll
        for (int mi = 0; mi < 4; mi++) {
            const int r = wm + mi * 16 + grp;
            a[mi][0] = As[r * GSTR32 + q];
            a[mi][1] = As[(r + 8) * GSTR32 + q];
            a[mi][2] = As[r * GSTR32 + q + 4];
            a[mi][3] = As[(r + 8) * GSTR32 + q + 4];
        }
#pragma unroll
        for (int ni = 0; ni < 4; ni++) {
            const int n = wn + ni * 8 + grp;
            b[ni][0] = Bs[n * GSTR32 + q];
            b[ni][1] = Bs[n * GSTR32 + q + 4];
        }
#pragma unroll
        for (int mi = 0; mi < 4; mi++)
#pragma unroll
            for (int ni = 0; ni < 4; ni++)
                mma_f16(acc[mi][ni], a[mi], b[ni]);

        if (more) {
            __syncthreads();
            store_tiles();
            __syncthreads();
        }
    }

#pragma unroll
    for (int mi = 0; mi < 4; mi++) {
#pragma unroll
        for (int half = 0; half < 2; half++) {
            const int gm = bm + wm + mi * 16 + grp + half * 8;
            if (gm >= MT) continue;
            const int bb = gm / NN;
            const int nn = gm - bb * NN;
#pragma unroll
            for (int ni = 0; ni < 4; ni++) {
                const int gn = bn + wn + ni * 8 + 2 * q;
                float2 o;
                o.x = acc[mi][ni][half * 2 + 0] + bias[gn];
                o.y = acc[mi][ni][half * 2 + 1] + bias[gn + 1];
                if (MODE == 0) {
                    *reinterpret_cast<float2*>(Y + (size_t)gm * DD + gn) = o;
                } else {
                    const int h  = gn >> 6;
                    const int hd = gn & 63;
                    *reinterpret_cast<float2*>(
                        Y + (((size_t)(bb * HH + h)) * NN + nn) * HDIM + hd) = o;
                }
            }
        }
    }
}

// ---------------- RoPE on q and k (in-place, rows n >= PREFIX) ----------------
__global__ __launch_bounds__(256)
void rope_kernel(const float* __restrict__ sinp, const float* __restrict__ cosp)
{
    const int idx = blockIdx.x * blockDim.x + threadIdx.x;
    const int total = BB * HH * NP * 32;
    if (idx >= total) return;
    const int d  = idx & 31;
    const int r  = idx >> 5;
    const int n  = r % NP;
    const int bh = r / NP;
    const size_t base = ((size_t)bh * NN + (n + PREFIX)) * HDIM;

    const float c1 = cosp[n * HDIM + d];
    const float c2 = cosp[n * HDIM + d + 32];
    const float s1 = sinp[n * HDIM + d];
    const float s2 = sinp[n * HDIM + d + 32];

    const float q1 = g_q[base + d], q2 = g_q[base + d + 32];
    g_q[base + d]      = q1 * c1 - q2 * s1;
    g_q[base + d + 32] = q2 * c2 + q1 * s2;

    const float k1 = g_k[base + d], k2 = g_k[base + d + 32];
    g_k[base + d]      = k1 * c1 - k2 * s1;
    g_k[base + d + 32] = k2 * c2 + k1 * s2;
}

// ---------------- fp16 tensor-core flash attention ----------------
// 128 q-rows per CTA, 64 k-rows per tile, 8 warps each owning 16 q-rows.
// P stays in registers (mma C-layout == A-layout for the warp's stripe)
// -> only 2 __syncthreads per k-tile, no P smem traffic.
#define AQ 128
#define AKT 64
#define ASTR32 36       // row stride in uint32 (72 halves); bank = 4*grp+q bijection

__global__ __launch_bounds__(256, 2)
void attn_f16_kernel(float* __restrict__ ctx)
{
    __shared__ __align__(16) uint32_t Qs[AQ  * ASTR32];
    __shared__ __align__(16) uint32_t Ks[AKT * ASTR32];
    __shared__ __align__(16) uint32_t Vt[HDIM * ASTR32];   // V transposed [d][kt]

    const int tid  = threadIdx.x;
    const int lane = tid & 31;
    const int warp = tid >> 5;
    const int q    = lane & 3;
    const int grp  = lane >> 2;
    const int bh   = blockIdx.y;
    const int q0   = blockIdx.x * AQ;

    const float* __restrict__ Qg = g_q + (size_t)bh * NN * HDIM;
    const float* __restrict__ Kg = g_k + (size_t)bh * NN * HDIM;
    const float* __restrict__ Vg = g_v + (size_t)bh * NN * HDIM;

    // load Q tile (fp16), coalesced, zero-padded
#pragma unroll
    for (int it = 0; it < 8; it++) {
        const int i  = tid + it * 256;
        const int r  = i >> 4;
        const int d4 = (i & 15) * 4;
        float4 v = make_float4(0.f, 0.f, 0.f, 0.f);
        if (q0 + r < NN)
            v = *reinterpret_cast<const float4*>(Qg + (size_t)(q0 + r) * HDIM + d4);
        uint2 u;
        u.x = fpack(v.x, v.y); u.y = fpack(v.z, v.w);
        *reinterpret_cast<uint2*>(&Qs[r * ASTR32 + (d4 >> 1)]) = u;
    }

    float m0 = -INFINITY, m1 = -INFINITY, l0 = 0.f, l1 = 0.f;
    float acc_o[8][4];
#pragma unroll
    for (int nt = 0; nt < 8; nt++)
#pragma unroll
        for (int c = 0; c < 4; c++) acc_o[nt][c] = 0.f;

    const int row_s = warp * 16 + grp;
    const float scale = 0.125f;                 // HD^-0.5
    const int nkt = (NN + AKT - 1) / AKT;       // 17

    for (int t = 0; t < nkt; t++) {
        const int k0 = t * AKT;
        __syncthreads();   // all warps done reading Ks (QK) and Vt (PV) of prev tile

        // K tile -> Ks [kt][d]; V tile -> Vt [d][kt] (transposed)
#pragma unroll
        for (int it = 0; it < 4; it++) {
            const int i   = tid + it * 256;
            const int ktr = i >> 4;
            const int d4  = (i & 15) * 4;
            float4 kv = make_float4(0.f, 0.f, 0.f, 0.f);
            if (k0 + ktr < NN)
                kv = *reinterpret_cast<const float4*>(Kg + (size_t)(k0 + ktr) * HDIM + d4);
            uint2 u;
            u.x = fpack(kv.x, kv.y); u.y = fpack(kv.z, kv.w);
            *reinterpret_cast<uint2*>(&Ks[ktr * ASTR32 + (d4 >> 1)]) = u;
        }
#pragma unroll
        for (int it = 0; it < 4; it++) {
            const int i   = tid + it * 256;
            const int ktr = i & 63;
            const int d4  = (i >> 6) * 4;
            float4 vv = make_float4(0.f, 0.f, 0.f, 0.f);
            if (k0 + ktr < NN)
                vv = *reinterpret_cast<const float4*>(Vg + (size_t)(k0 + ktr) * HDIM + d4);
            __half* Vh = reinterpret_cast<__half*>(Vt);
            Vh[(d4 + 0) * (2 * ASTR32) + ktr] = __float2half_rn(vv.x);
            Vh[(d4 + 1) * (2 * ASTR32) + ktr] = __float2half_rn(vv.y);
            Vh[(d4 + 2) * (2 * ASTR32) + ktr] = __float2half_rn(vv.z);
            Vh[(d4 + 3) * (2 * ASTR32) + ktr] = __float2half_rn(vv.w);
        }
        __syncthreads();

        // ---- S = Q K^T ----
        float acc_s[8][4];
#pragma unroll
        for (int nt = 0; nt < 8; nt++)
#pragma unroll
            for (int c = 0; c < 4; c++) acc_s[nt][c] = 0.f;

#pragma unroll
        for (int ks = 0; ks < 4; ks++) {        // d = 16*ks .. +15
            uint32_t a[4];
            a[0] = Qs[row_s * ASTR32 + 8 * ks + q];
            a[1] = Qs[(row_s + 8) * ASTR32 + 8 * ks + q];
            a[2] = Qs[row_s * ASTR32 + 8 * ks + q + 4];
            a[3] = Qs[(row_s + 8) * ASTR32 + 8 * ks + q + 4];
#pragma unroll
            for (int nt = 0; nt < 8; nt++) {
                uint32_t b[2];
                b[0] = Ks[(nt * 8 + grp) * ASTR32 + 8 * ks + q];
                b[1] = Ks[(nt * 8 + grp) * ASTR32 + 8 * ks + q + 4];
                mma_f16(acc_s[nt], a, b);
            }
        }

        // ---- online softmax (fp32) ----
        float r0m = -INFINITY, r1m = -INFINITY;
#pragma unroll
        for (int nt = 0; nt < 8; nt++) {
            const int c = k0 + nt * 8 + 2 * q;
            const float s0 = (c     < NN) ? acc_s[nt][0] * scale : -INFINITY;
            const float s1 = (c + 1 < NN) ? acc_s[nt][1] * scale : -INFINITY;
            const float s2 = (c     < NN) ? acc_s[nt][2] * scale : -INFINITY;
            const float s3 = (c + 1 < NN) ? acc_s[nt][3] * scale : -INFINITY;
            acc_s[nt][0] = s0; acc_s[nt][1] = s1;
            acc_s[nt][2] = s2; acc_s[nt][3] = s3;
            r0m = fmaxf(r0m, fmaxf(s0, s1));
            r1m = fmaxf(r1m, fmaxf(s2, s3));
        }
        r0m = fmaxf(r0m, __shfl_xor_sync(0xffffffffu, r0m, 1));
        r0m = fmaxf(r0m, __shfl_xor_sync(0xffffffffu, r0m, 2));
        r1m = fmaxf(r1m, __shfl_xor_sync(0xffffffffu, r1m, 1));
        r1m = fmaxf(r1m, __shfl_xor_sync(0xffffffffu, r1m, 2));

        const float m0n = fmaxf(m0, r0m);
        const float m1n = fmaxf(m1, r1m);
        const float a0  = __expf(m0 - m0n);
        const float a1  = __expf(m1 - m1n);

        float sum0 = 0.f, sum1 = 0.f;
#pragma unroll
        for (int nt = 0; nt < 8; nt++) {
            const float p0 = __expf(acc_s[nt][0] - m0n);
            const float p1 = __expf(acc_s[nt][1] - m0n);
            const float p2 = __expf(acc_s[nt][2] - m1n);
            const float p3 = __expf(acc_s[nt][3] - m1n);
            acc_s[nt][0] = p0; acc_s[nt][1] = p1;
            acc_s[nt][2] = p2; acc_s[nt][3] = p3;
            sum0 += p0 + p1; sum1 += p2 + p3;
        }
        sum0 += __shfl_xor_sync(0xffffffffu, sum0, 1);
        sum0 += __shfl_xor_sync(0xffffffffu, sum0, 2);
        sum1 += __shfl_xor_sync(0xffffffffu, sum1, 1);
        sum1 += __shfl_xor_sync(0xffffffffu, sum1, 2);

        l0 = l0 * a0 + sum0;
        l1 = l1 * a1 + sum1;
        m0 = m0n; m1 = m1n;

#pragma unroll
        for (int nt = 0; nt < 8; nt++) {
            acc_o[nt][0] *= a0; acc_o[nt][1] *= a0;
            acc_o[nt][2] *= a1; acc_o[nt][3] *= a1;
        }

        // ---- O += P V : P packed from registers (no smem round-trip) ----
#pragma unroll
        for (int ks = 0; ks < 4; ks++) {        // kt = 16*ks .. +15
            uint32_t a[4];
            a[0] = fpack(acc_s[2 * ks][0],     acc_s[2 * ks][1]);
            a[1] = fpack(acc_s[2 * ks][2],     acc_s[2 * ks][3]);
            a[2] = fpack(acc_s[2 * ks + 1][0], acc_s[2 * ks + 1][1]);
            a[3] = fpack(acc_s[2 * ks + 1][2], acc_s[2 * ks + 1][3]);
#pragma unroll
            for (int nt = 0; nt < 8; nt++) {
                uint32_t b[2];
                b[0] = Vt[(nt * 8 + grp) * ASTR32 + 8 * ks + q];
                b[1] = Vt[(nt * 8 + grp) * ASTR32 + 8 * ks + q + 4];
                mma_f16(acc_o[nt], a, b);
            }
        }
    }

    // ---- epilogue ----
    const int b = bh / HH;
    const int h = bh % HH;
    const float inv0 = 1.f / l0;
    const float inv1 = 1.f / l1;
    const int r0g = q0 + warp * 16 + grp;
    const int r1g = r0g + 8;
#pragma unroll
    for (int nt = 0; nt < 8; nt++) {
        const int d = h * HDIM + nt * 8 + 2 * q;
        if (r0g < NN) {
            float2 o; o.x = acc_o[nt][0] * inv0; o.y = acc_o[nt][1] * inv0;
            *reinterpret_cast<float2*>(ctx + ((size_t)(b * NN + r0g)) * DD + d) = o;
        }
        if (r1g < NN) {
            float2 o; o.x = acc_o[nt][2] * inv1; o.y = acc_o[nt][3] * inv1;
            *reinterpret_cast<float2*>(ctx + ((size_t)(b * NN + r1g)) * DD + d) = o;
        }
    }
}

// ---------------- launch ----------------
extern "C" void kernel_launch(void* const* d_in, const int* in_sizes, int n_in,
                              void* d_out, int out_size)
{
    const float* hs  = (const float*)d_in[0];
    const float* sn  = (const float*)d_in[1];
    const float* cs  = (const float*)d_in[2];
    const float* Wq  = (const float*)d_in[3];
    const float* bq  = (const float*)d_in[4];
    const float* Wk  = (const float*)d_in[5];
    const float* bk  = (const float*)d_in[6];
    const float* Wv  = (const float*)d_in[7];
    const float* bv  = (const float*)d_in[8];
    const float* Wo  = (const float*)d_in[9];
    const float* bo  = (const float*)d_in[10];
    float* out = (float*)d_out;

    float *q, *k, *v, *ctx;
    cudaGetSymbolAddress((void**)&q,   g_q);
    cudaGetSymbolAddress((void**)&k,   g_k);
    cudaGetSymbolAddress((void**)&v,   g_v);
    cudaGetSymbolAddress((void**)&ctx, g_ctx);

    const dim3 ggrid(DD / 128, (MT + 127) / 128);   // 8 x 129
    gemm_f16_kernel<1><<<ggrid, 256>>>(hs, Wq, bq, q);
    gemm_f16_kernel<1><<<ggrid, 256>>>(hs, Wk, bk, k);
    gemm_f16_kernel<1><<<ggrid, 256>>>(hs, Wv, bv, v);

    const int rope_threads = BB * HH * NP * 32;
    rope_kernel<<<(rope_threads + 255) / 256, 256>>>(sn, cs);

    const dim3 agrid((NN + AQ - 1) / AQ, BB * HH);  // 9 x 256
    attn_f16_kernel<<<agrid, 256>>>(ctx);

    gemm_f16_kernel<0><<<ggrid, 256>>>(ctx, Wo, bo, out);
}

// round 12
// speedup vs baseline: 7.2997x; 1.2555x over previous
#include <cuda_runtime.h>
#include <cuda_fp16.h>
#include <math.h>
#include <stdint.h>

#define BB 16
#define NN 1029
#define HH 16
#define HDIM 64
#define DD 1024
#define MT (BB*NN)          // 16464 rows
#define NP 1024             // rope table length
#define PREFIX (NN-NP)      // 5

// ---------------- scratch (no allocations allowed) ----------------
__device__ __half g_hs[(size_t)MT*DD];
__device__ __half g_wq[(size_t)DD*DD];
__device__ __half g_wk[(size_t)DD*DD];
__device__ __half g_wv[(size_t)DD*DD];
__device__ __half g_wo[(size_t)DD*DD];
__device__ __half g_q[(size_t)BB*HH*NN*HDIM];
__device__ __half g_k[(size_t)BB*HH*NN*HDIM];
__device__ __half g_v[(size_t)BB*HH*NN*HDIM];
__device__ __half g_ctx[(size_t)BB*NN*DD];

// ---------------- helpers ----------------
__device__ __forceinline__ uint32_t fpack(float a, float b) {
    __half2 h = __floats2half2_rn(a, b);
    return *reinterpret_cast<uint32_t*>(&h);
}

__device__ __forceinline__ void mma_f16(float* d, const uint32_t* a, const uint32_t* b) {
    asm volatile(
        "mma.sync.aligned.m16n8k16.row.col.f32.f16.f16.f32 "
        "{%0,%1,%2,%3},{%4,%5,%6,%7},{%8,%9},{%0,%1,%2,%3};\n"
        : "+f"(d[0]), "+f"(d[1]), "+f"(d[2]), "+f"(d[3])
        : "r"(a[0]), "r"(a[1]), "r"(a[2]), "r"(a[3]), "r"(b[0]), "r"(b[1]));
}

__device__ __forceinline__ void cpa16(uint32_t dst, const void* src, bool p) {
    asm volatile("cp.async.ca.shared.global [%0], [%1], 16, %2;\n"
                 :: "r"(dst), "l"(src), "r"(p ? 16 : 0));
}
#define CPA_COMMIT() asm volatile("cp.async.commit_group;\n" ::: "memory")
#define CPA_WAIT(n)  asm volatile("cp.async.wait_group %0;\n" :: "n"(n) : "memory")

// ---------------- fp32 -> fp16 convert ----------------
__global__ __launch_bounds__(256)
void f2h_kernel(const float4* __restrict__ src, uint2* __restrict__ dst, int n4)
{
    const int i = blockIdx.x * blockDim.x + threadIdx.x;
    if (i >= n4) return;
    const float4 v = src[i];
    uint2 u;
    u.x = fpack(v.x, v.y);
    u.y = fpack(v.z, v.w);
    dst[i] = u;
}

// ---------------- fp16 tensor-core GEMM, 3-stage cp.async pipeline ----------------
// Y[m,n] = sum_k X[m,k]*W[n,k] + bias[n]
// MODE 0: float output, row-major (M x D); MODE 1: half output, (B,H,N,HD)
// CTA tile 128x128, BK=32 (2 x m16n8k16 per stage). 8 warps of 64x32.
// smem row stride 20 u32 (40 halves): bank (20*grp+q) mod 32 is a bijection.
#define GBK 32
#define GSTR 20
#define GTILE (128*GSTR)     // u32 per matrix per stage
#define GSTAGES 3
#define GEMM_SMEM (GSTAGES*2*GTILE*4)   // 61440 bytes

template<int MODE>
__global__ __launch_bounds__(256, 2)
void gemm_f16_kernel(const __half* __restrict__ X, const __half* __restrict__ W,
                     const float* __restrict__ bias, void* __restrict__ Yv)
{
    extern __shared__ uint32_t smg[];
    const uint32_t sbase = (uint32_t)__cvta_generic_to_shared(smg);

    const int tid  = threadIdx.x;
    const int lane = tid & 31;
    const int warp = tid >> 5;
    const int q    = lane & 3;
    const int grp  = lane >> 2;
    const int wm   = (warp >> 2) * 64;
    const int wn   = (warp & 3) * 32;

    const int bm = blockIdx.y * 128;
    const int bn = blockIdx.x * 128;

    float acc[4][4][4];
#pragma unroll
    for (int mi = 0; mi < 4; mi++)
#pragma unroll
        for (int ni = 0; ni < 4; ni++)
#pragma unroll
            for (int c = 0; c < 4; c++) acc[mi][ni][c] = 0.f;

    // per-stage loader: 128 rows x 32 halves per matrix = 512 x 16B chunks
    // thread covers 2 chunks per matrix: c = tid + it*256, row=c>>2, k8=(c&3)*8
    auto issue_stage = [&](int st, int k0) {
#pragma unroll
        for (int it = 0; it < 2; it++) {
            const int c   = tid + it * 256;
            const int row = c >> 2;
            const int k8  = (c & 3) * 8;
            const int du  = row * GSTR + (c & 3) * 4;
            const int gm  = bm + row;
            cpa16(sbase + (st * 2 * GTILE + du) * 4,
                  X + (size_t)gm * DD + k0 + k8, gm < MT);
            cpa16(sbase + (st * 2 * GTILE + GTILE + du) * 4,
                  W + (size_t)(bn + row) * DD + k0 + k8, true);
        }
    };

    issue_stage(0, 0);  CPA_COMMIT();
    issue_stage(1, GBK); CPA_COMMIT();

    const int nk = DD / GBK;    // 32
    int stage = 0;

    for (int kt = 0; kt < nk; kt++) {
        CPA_WAIT(1);
        __syncthreads();

        const uint32_t* A = smg + stage * 2 * GTILE;
        const uint32_t* B = A + GTILE;
#pragma unroll
        for (int st = 0; st < 2; st++) {
            const int ko = 8 * st;
            uint32_t a[4][4], b[4][2];
#pragma unroll
            for (int mi = 0; mi < 4; mi++) {
                const int r = wm + mi * 16 + grp;
                a[mi][0] = A[r * GSTR + ko + q];
                a[mi][1] = A[(r + 8) * GSTR + ko + q];
                a[mi][2] = A[r * GSTR + ko + q + 4];
                a[mi][3] = A[(r + 8) * GSTR + ko + q + 4];
            }
#pragma unroll
            for (int ni = 0; ni < 4; ni++) {
                const int n = wn + ni * 8 + grp;
                b[ni][0] = B[n * GSTR + ko + q];
                b[ni][1] = B[n * GSTR + ko + q + 4];
            }
#pragma unroll
            for (int mi = 0; mi < 4; mi++)
#pragma unroll
                for (int ni = 0; ni < 4; ni++)
                    mma_f16(acc[mi][ni], a[mi], b[ni]);
        }

        if (kt + 2 < nk) issue_stage((kt + 2) % GSTAGES, (kt + 2) * GBK);
        CPA_COMMIT();
        stage = (stage + 1) % GSTAGES;
    }

    // epilogue
#pragma unroll
    for (int mi = 0; mi < 4; mi++) {
#pragma unroll
        for (int half = 0; half < 2; half++) {
            const int gm = bm + wm + mi * 16 + grp + half * 8;
            if (gm >= MT) continue;
            const int bb = gm / NN;
            const int nn = gm - bb * NN;
#pragma unroll
            for (int ni = 0; ni < 4; ni++) {
                const int gn = bn + wn + ni * 8 + 2 * q;
                const float ox = acc[mi][ni][half * 2 + 0] + bias[gn];
                const float oy = acc[mi][ni][half * 2 + 1] + bias[gn + 1];
                if (MODE == 0) {
                    float2 o; o.x = ox; o.y = oy;
                    *reinterpret_cast<float2*>((float*)Yv + (size_t)gm * DD + gn) = o;
                } else {
                    const int h  = gn >> 6;
                    const int hd = gn & 63;
                    *reinterpret_cast<__half2*>(
                        (__half*)Yv + (((size_t)(bb * HH + h)) * NN + nn) * HDIM + hd)
                        = __floats2half2_rn(ox, oy);
                }
            }
        }
    }
}

// ---------------- RoPE on fp16 q and k (in-place, rows n >= PREFIX) ----------------
__global__ __launch_bounds__(256)
void rope_kernel(const float* __restrict__ sinp, const float* __restrict__ cosp)
{
    const int idx = blockIdx.x * blockDim.x + threadIdx.x;
    const int total = BB * HH * NP * 16;
    if (idx >= total) return;
    const int d2 = idx & 15;            // handles d = 2*d2, 2*d2+1 (and +32)
    const int r  = idx >> 4;
    const int n  = r % NP;
    const int bh = r / NP;
    const size_t base = ((size_t)bh * NN + (n + PREFIX)) * HDIM;
    const int d = 2 * d2;

    const float2 c1 = *reinterpret_cast<const float2*>(cosp + n * HDIM + d);
    const float2 c2 = *reinterpret_cast<const float2*>(cosp + n * HDIM + d + 32);
    const float2 s1 = *reinterpret_cast<const float2*>(sinp + n * HDIM + d);
    const float2 s2 = *reinterpret_cast<const float2*>(sinp + n * HDIM + d + 32);

    {
        const float2 q1 = __half22float2(*reinterpret_cast<__half2*>(g_q + base + d));
        const float2 q2 = __half22float2(*reinterpret_cast<__half2*>(g_q + base + d + 32));
        *reinterpret_cast<__half2*>(g_q + base + d) =
            __floats2half2_rn(q1.x * c1.x - q2.x * s1.x, q1.y * c1.y - q2.y * s1.y);
        *reinterpret_cast<__half2*>(g_q + base + d + 32) =
            __floats2half2_rn(q2.x * c2.x + q1.x * s2.x, q2.y * c2.y + q1.y * s2.y);
    }
    {
        const float2 k1 = __half22float2(*reinterpret_cast<__half2*>(g_k + base + d));
        const float2 k2 = __half22float2(*reinterpret_cast<__half2*>(g_k + base + d + 32));
        *reinterpret_cast<__half2*>(g_k + base + d) =
            __floats2half2_rn(k1.x * c1.x - k2.x * s1.x, k1.y * c1.y - k2.y * s1.y);
        *reinterpret_cast<__half2*>(g_k + base + d + 32) =
            __floats2half2_rn(k2.x * c2.x + k1.x * s2.x, k2.y * c2.y + k1.y * s2.y);
    }
}

// ---------------- fp16 tensor-core flash attention ----------------
// 128 q-rows per CTA, 64 k-rows per tile, 8 warps each owning 16 q-rows.
// Q/K via cp.async from fp16 global; V register-transposed; P register-resident.
#define AQ 128
#define AKT 64
#define ASTR32 36       // row stride in u32 (72 halves); bank 4*grp+q bijection

__global__ __launch_bounds__(256, 2)
void attn_f16_kernel(__half* __restrict__ ctx)
{
    __shared__ __align__(16) uint32_t Qs[AQ  * ASTR32];
    __shared__ __align__(16) uint32_t Ks[AKT * ASTR32];
    __shared__ __align__(16) uint32_t Vt[HDIM * ASTR32];   // V^T [d][kt]

    const uint32_t qbase = (uint32_t)__cvta_generic_to_shared(Qs);
    const uint32_t kbase = (uint32_t)__cvta_generic_to_shared(Ks);

    const int tid  = threadIdx.x;
    const int lane = tid & 31;
    const int warp = tid >> 5;
    const int q    = lane & 3;
    const int grp  = lane >> 2;
    const int bh   = blockIdx.y;
    const int q0   = blockIdx.x * AQ;

    const __half* __restrict__ Qg = g_q + (size_t)bh * NN * HDIM;
    const __half* __restrict__ Kg = g_k + (size_t)bh * NN * HDIM;
    const __half* __restrict__ Vg = g_v + (size_t)bh * NN * HDIM;

    // Q tile via cp.async: 128 rows x 8 chunks
#pragma unroll
    for (int it = 0; it < 4; it++) {
        const int c  = tid + it * 256;
        const int r  = c >> 3;
        const int k8 = (c & 7) * 8;
        cpa16(qbase + (r * ASTR32 + (c & 7) * 4) * 4,
              Qg + (size_t)(q0 + r) * HDIM + k8, q0 + r < NN);
    }
    CPA_COMMIT();

    float m0 = -INFINITY, m1 = -INFINITY, l0 = 0.f, l1 = 0.f;
    float acc_o[8][4];
#pragma unroll
    for (int nt = 0; nt < 8; nt++)
#pragma unroll
        for (int c = 0; c < 4; c++) acc_o[nt][c] = 0.f;

    const int row_s = warp * 16 + grp;
    const float scale = 0.125f;
    const int nkt = (NN + AKT - 1) / AKT;       // 17

    for (int t = 0; t < nkt; t++) {
        const int k0 = t * AKT;
        __syncthreads();   // previous tile consumers done

        // K tile via cp.async: 64 rows x 8 chunks
#pragma unroll
        for (int it = 0; it < 2; it++) {
            const int c   = tid + it * 256;
            const int ktr = c >> 3;
            const int k8  = (c & 7) * 8;
            cpa16(kbase + (ktr * ASTR32 + (c & 7) * 4) * 4,
                  Kg + (size_t)(k0 + ktr) * HDIM + k8, k0 + ktr < NN);
        }
        CPA_COMMIT();

        // V tile -> Vt transposed [d][kt]
        __half* Vh = reinterpret_cast<__half*>(Vt);
#pragma unroll
        for (int it = 0; it < 4; it++) {
            const int c   = tid + it * 256;
            const int ktr = c & 63;
            const int d4  = (c >> 6) * 4;
            __half vv[4];
            if (k0 + ktr < NN) {
                *reinterpret_cast<uint2*>(vv) =
                    *reinterpret_cast<const uint2*>(Vg + (size_t)(k0 + ktr) * HDIM + d4);
            } else {
                vv[0] = vv[1] = vv[2] = vv[3] = __float2half(0.f);
            }
            Vh[(d4 + 0) * (2 * ASTR32) + ktr] = vv[0];
            Vh[(d4 + 1) * (2 * ASTR32) + ktr] = vv[1];
            Vh[(d4 + 2) * (2 * ASTR32) + ktr] = vv[2];
            Vh[(d4 + 3) * (2 * ASTR32) + ktr] = vv[3];
        }
        CPA_WAIT(0);
        __syncthreads();

        // ---- S = Q K^T ----
        float acc_s[8][4];
#pragma unroll
        for (int nt = 0; nt < 8; nt++)
#pragma unroll
            for (int c = 0; c < 4; c++) acc_s[nt][c] = 0.f;

#pragma unroll
        for (int ks = 0; ks < 4; ks++) {
            uint32_t a[4];
            a[0] = Qs[row_s * ASTR32 + 8 * ks + q];
            a[1] = Qs[(row_s + 8) * ASTR32 + 8 * ks + q];
            a[2] = Qs[row_s * ASTR32 + 8 * ks + q + 4];
            a[3] = Qs[(row_s + 8) * ASTR32 + 8 * ks + q + 4];
#pragma unroll
            for (int nt = 0; nt < 8; nt++) {
                uint32_t b[2];
                b[0] = Ks[(nt * 8 + grp) * ASTR32 + 8 * ks + q];
                b[1] = Ks[(nt * 8 + grp) * ASTR32 + 8 * ks + q + 4];
                mma_f16(acc_s[nt], a, b);
            }
        }

        // ---- online softmax (fp32) ----
        float r0m = -INFINITY, r1m = -INFINITY;
#pragma unroll
        for (int nt = 0; nt < 8; nt++) {
            const int c = k0 + nt * 8 + 2 * q;
            const float s0 = (c     < NN) ? acc_s[nt][0] * scale : -INFINITY;
            const float s1 = (c + 1 < NN) ? acc_s[nt][1] * scale : -INFINITY;
            const float s2 = (c     < NN) ? acc_s[nt][2] * scale : -INFINITY;
            const float s3 = (c + 1 < NN) ? acc_s[nt][3] * scale : -INFINITY;
            acc_s[nt][0] = s0; acc_s[nt][1] = s1;
            acc_s[nt][2] = s2; acc_s[nt][3] = s3;
            r0m = fmaxf(r0m, fmaxf(s0, s1));
            r1m = fmaxf(r1m, fmaxf(s2, s3));
        }
        r0m = fmaxf(r0m, __shfl_xor_sync(0xffffffffu, r0m, 1));
        r0m = fmaxf(r0m, __shfl_xor_sync(0xffffffffu, r0m, 2));
        r1m = fmaxf(r1m, __shfl_xor_sync(0xffffffffu, r1m, 1));
        r1m = fmaxf(r1m, __shfl_xor_sync(0xffffffffu, r1m, 2));

        const float m0n = fmaxf(m0, r0m);
        const float m1n = fmaxf(m1, r1m);
        const float a0  = __expf(m0 - m0n);
        const float a1  = __expf(m1 - m1n);

        float sum0 = 0.f, sum1 = 0.f;
#pragma unroll
        for (int nt = 0; nt < 8; nt++) {
            const float p0 = __expf(acc_s[nt][0] - m0n);
            const float p1 = __expf(acc_s[nt][1] - m0n);
            const float p2 = __expf(acc_s[nt][2] - m1n);
            const float p3 = __expf(acc_s[nt][3] - m1n);
            acc_s[nt][0] = p0; acc_s[nt][1] = p1;
            acc_s[nt][2] = p2; acc_s[nt][3] = p3;
            sum0 += p0 + p1; sum1 += p2 + p3;
        }
        sum0 += __shfl_xor_sync(0xffffffffu, sum0, 1);
        sum0 += __shfl_xor_sync(0xffffffffu, sum0, 2);
        sum1 += __shfl_xor_sync(0xffffffffu, sum1, 1);
        sum1 += __shfl_xor_sync(0xffffffffu, sum1, 2);

        l0 = l0 * a0 + sum0;
        l1 = l1 * a1 + sum1;
        m0 = m0n; m1 = m1n;

#pragma unroll
        for (int nt = 0; nt < 8; nt++) {
            acc_o[nt][0] *= a0; acc_o[nt][1] *= a0;
            acc_o[nt][2] *= a1; acc_o[nt][3] *= a1;
        }

        // ---- O += P V : P packed from registers ----
#pragma unroll
        for (int ks = 0; ks < 4; ks++) {
            uint32_t a[4];
            a[0] = fpack(acc_s[2 * ks][0],     acc_s[2 * ks][1]);
            a[1] = fpack(acc_s[2 * ks][2],     acc_s[2 * ks][3]);
            a[2] = fpack(acc_s[2 * ks + 1][0], acc_s[2 * ks + 1][1]);
            a[3] = fpack(acc_s[2 * ks + 1][2], acc_s[2 * ks + 1][3]);
#pragma unroll
            for (int nt = 0; nt < 8; nt++) {
                uint32_t b[2];
                b[0] = Vt[(nt * 8 + grp) * ASTR32 + 8 * ks + q];
                b[1] = Vt[(nt * 8 + grp) * ASTR32 + 8 * ks + q + 4];
                mma_f16(acc_o[nt], a, b);
            }
        }
    }

    // ---- epilogue: O / l -> ctx (half) ----
    const int b = bh / HH;
    const int h = bh % HH;
    const float inv0 = 1.f / l0;
    const float inv1 = 1.f / l1;
    const int r0g = q0 + warp * 16 + grp;
    const int r1g = r0g + 8;
#pragma unroll
    for (int nt = 0; nt < 8; nt++) {
        const int d = h * HDIM + nt * 8 + 2 * q;
        if (r0g < NN)
            *reinterpret_cast<__half2*>(ctx + ((size_t)(b * NN + r0g)) * DD + d)
                = __floats2half2_rn(acc_o[nt][0] * inv0, acc_o[nt][1] * inv0);
        if (r1g < NN)
            *reinterpret_cast<__half2*>(ctx + ((size_t)(b * NN + r1g)) * DD + d)
                = __floats2half2_rn(acc_o[nt][2] * inv1, acc_o[nt][3] * inv1);
    }
}

// ---------------- launch ----------------
extern "C" void kernel_launch(void* const* d_in, const int* in_sizes, int n_in,
                              void* d_out, int out_size)
{
    const float* hs  = (const float*)d_in[0];
    const float* sn  = (const float*)d_in[1];
    const float* cs  = (const float*)d_in[2];
    const float* Wq  = (const float*)d_in[3];
    const float* bq  = (const float*)d_in[4];
    const float* Wk  = (const float*)d_in[5];
    const float* bk  = (const float*)d_in[6];
    const float* Wv  = (const float*)d_in[7];
    const float* bv  = (const float*)d_in[8];
    const float* Wo  = (const float*)d_in[9];
    const float* bo  = (const float*)d_in[10];
    float* out = (float*)d_out;

    __half *hsh, *wqh, *wkh, *wvh, *woh, *qh, *kh, *vh, *ctxh;
    cudaGetSymbolAddress((void**)&hsh, g_hs);
    cudaGetSymbolAddress((void**)&wqh, g_wq);
    cudaGetSymbolAddress((void**)&wkh, g_wk);
    cudaGetSymbolAddress((void**)&wvh, g_wv);
    cudaGetSymbolAddress((void**)&woh, g_wo);
    cudaGetSymbolAddress((void**)&qh,  g_q);
    cudaGetSymbolAddress((void**)&kh,  g_k);
    cudaGetSymbolAddress((void**)&vh,  g_v);
    cudaGetSymbolAddress((void**)&ctxh, g_ctx);

    cudaFuncSetAttribute(gemm_f16_kernel<0>,
                         cudaFuncAttributeMaxDynamicSharedMemorySize, GEMM_SMEM);
    cudaFuncSetAttribute(gemm_f16_kernel<1>,
                         cudaFuncAttributeMaxDynamicSharedMemorySize, GEMM_SMEM);

    // convert inputs to fp16 (once per replay; deterministic)
    const int n4hs = MT * DD / 4;
    const int n4w  = DD * DD / 4;
    f2h_kernel<<<(n4hs + 255) / 256, 256>>>((const float4*)hs, (uint2*)hsh, n4hs);
    f2h_kernel<<<(n4w + 255) / 256, 256>>>((const float4*)Wq, (uint2*)wqh, n4w);
    f2h_kernel<<<(n4w + 255) / 256, 256>>>((const float4*)Wk, (uint2*)wkh, n4w);
    f2h_kernel<<<(n4w + 255) / 256, 256>>>((const float4*)Wv, (uint2*)wvh, n4w);
    f2h_kernel<<<(n4w + 255) / 256, 256>>>((const float4*)Wo, (uint2*)woh, n4w);

    const dim3 ggrid(DD / 128, (MT + 127) / 128);   // 8 x 129
    gemm_f16_kernel<1><<<ggrid, 256, GEMM_SMEM>>>(hsh, wqh, bq, qh);
    gemm_f16_kernel<1><<<ggrid, 256, GEMM_SMEM>>>(hsh, wkh, bk, kh);
    gemm_f16_kernel<1><<<ggrid, 256, GEMM_SMEM>>>(hsh, wvh, bv, vh);

    const int rope_threads = BB * HH * NP * 16;
    rope_kernel<<<(rope_threads + 255) / 256, 256>>>(sn, cs);

    const dim3 agrid((NN + AQ - 1) / AQ, BB * HH);  // 9 x 256
    attn_f16_kernel<<<agrid, 256>>>(ctxh);

    gemm_f16_kernel<0><<<ggrid, 256, GEMM_SMEM>>>(ctxh, woh, bo, out);
}

// round 15
// speedup vs baseline: 8.9629x; 1.2278x over previous
#include <cuda_runtime.h>
#include <cuda_fp16.h>
#include <math.h>
#include <stdint.h>

#define BB 16
#define NN 1029
#define HH 16
#define HDIM 64
#define DD 1024
#define MT (BB*NN)          // 16464 rows
#define NP 1024             // rope table length
#define PREFIX (NN-NP)      // 5

// ---------------- scratch (no allocations allowed) ----------------
__device__ __half g_hs[(size_t)MT*DD];
__device__ __half g_wq[(size_t)DD*DD];
__device__ __half g_wk[(size_t)DD*DD];
__device__ __half g_wv[(size_t)DD*DD];
__device__ __half g_wo[(size_t)DD*DD];
__device__ __half g_q[(size_t)BB*HH*NN*HDIM];
__device__ __half g_k[(size_t)BB*HH*NN*HDIM];
__device__ __half g_v[(size_t)BB*HH*NN*HDIM];
__device__ __half g_ctx[(size_t)BB*NN*DD];

// ---------------- helpers ----------------
__device__ __forceinline__ uint32_t fpack(float a, float b) {
    __half2 h = __floats2half2_rn(a, b);
    return *reinterpret_cast<uint32_t*>(&h);
}

__device__ __forceinline__ void mma_f16(float* d, const uint32_t* a, const uint32_t* b) {
    asm volatile(
        "mma.sync.aligned.m16n8k16.row.col.f32.f16.f16.f32 "
        "{%0,%1,%2,%3},{%4,%5,%6,%7},{%8,%9},{%0,%1,%2,%3};\n"
        : "+f"(d[0]), "+f"(d[1]), "+f"(d[2]), "+f"(d[3])
        : "r"(a[0]), "r"(a[1]), "r"(a[2]), "r"(a[3]), "r"(b[0]), "r"(b[1]));
}

__device__ __forceinline__ void cpa16(uint32_t dst, const void* src, bool p) {
    asm volatile("cp.async.ca.shared.global [%0], [%1], 16, %2;\n"
                 :: "r"(dst), "l"(src), "r"(p ? 16 : 0));
}
#define CPA_COMMIT() asm volatile("cp.async.commit_group;\n" ::: "memory")
#define CPA_WAIT(n)  asm volatile("cp.async.wait_group %0;\n" :: "n"(n) : "memory")

__device__ __forceinline__ void ldsm_x4(uint32_t* r, uint32_t addr) {
    asm volatile("ldmatrix.sync.aligned.m8n8.x4.shared.b16 {%0,%1,%2,%3}, [%4];\n"
                 : "=r"(r[0]), "=r"(r[1]), "=r"(r[2]), "=r"(r[3]) : "r"(addr));
}
__device__ __forceinline__ void ldsm_x4t(uint32_t* r, uint32_t addr) {
    asm volatile("ldmatrix.sync.aligned.m8n8.x4.trans.shared.b16 {%0,%1,%2,%3}, [%4];\n"
                 : "=r"(r[0]), "=r"(r[1]), "=r"(r[2]), "=r"(r[3]) : "r"(addr));
}

// ---------------- fp32 -> fp16 convert ----------------
__global__ __launch_bounds__(256)
void f2h_kernel(const float4* __restrict__ src, uint2* __restrict__ dst, int n4)
{
    const int i = blockIdx.x * blockDim.x + threadIdx.x;
    if (i >= n4) return;
    const float4 v = src[i];
    uint2 u;
    u.x = fpack(v.x, v.y);
    u.y = fpack(v.z, v.w);
    dst[i] = u;
}

// 4 weight matrices in one launch (grid.y selects)
__global__ __launch_bounds__(256)
void f2h4_kernel(const float4* s0, const float4* s1, const float4* s2, const float4* s3,
                 uint2* d0, uint2* d1, uint2* d2, uint2* d3, int n4)
{
    const int i = blockIdx.x * blockDim.x + threadIdx.x;
    if (i >= n4) return;
    const float4* s; uint2* d;
    switch (blockIdx.y) {
        case 0: s = s0; d = d0; break;
        case 1: s = s1; d = d1; break;
        case 2: s = s2; d = d2; break;
        default: s = s3; d = d3; break;
    }
    const float4 v = s[i];
    uint2 u;
    u.x = fpack(v.x, v.y);
    u.y = fpack(v.z, v.w);
    d[i] = u;
}

// ---------------- fp16 tensor-core GEMM, 3-stage cp.async pipeline ----------------
#define GBK 32
#define GSTR 20
#define GTILE (128*GSTR)
#define GSTAGES 3
#define GEMM_SMEM (GSTAGES*2*GTILE*4)   // 61440 bytes

template<int MODE>
__global__ __launch_bounds__(256, 2)
void gemm_f16_kernel(const __half* __restrict__ X, const __half* __restrict__ W,
                     const float* __restrict__ bias, void* __restrict__ Yv)
{
    extern __shared__ uint32_t smg[];
    const uint32_t sbase = (uint32_t)__cvta_generic_to_shared(smg);

    const int tid  = threadIdx.x;
    const int lane = tid & 31;
    const int warp = tid >> 5;
    const int q    = lane & 3;
    const int grp  = lane >> 2;
    const int wm   = (warp >> 2) * 64;
    const int wn   = (warp & 3) * 32;

    const int bm = blockIdx.y * 128;
    const int bn = blockIdx.x * 128;

    float acc[4][4][4];
#pragma unroll
    for (int mi = 0; mi < 4; mi++)
#pragma unroll
        for (int ni = 0; ni < 4; ni++)
#pragma unroll
            for (int c = 0; c < 4; c++) acc[mi][ni][c] = 0.f;

    auto issue_stage = [&](int st, int k0) {
#pragma unroll
        for (int it = 0; it < 2; it++) {
            const int c   = tid + it * 256;
            const int row = c >> 2;
            const int k8  = (c & 3) * 8;
            const int du  = row * GSTR + (c & 3) * 4;
            const int gm  = bm + row;
            cpa16(sbase + (st * 2 * GTILE + du) * 4,
                  X + (size_t)gm * DD + k0 + k8, gm < MT);
            cpa16(sbase + (st * 2 * GTILE + GTILE + du) * 4,
                  W + (size_t)(bn + row) * DD + k0 + k8, true);
        }
    };

    issue_stage(0, 0);  CPA_COMMIT();
    issue_stage(1, GBK); CPA_COMMIT();

    const int nk = DD / GBK;
    int stage = 0;

    for (int kt = 0; kt < nk; kt++) {
        CPA_WAIT(1);
        __syncthreads();

        const uint32_t* A = smg + stage * 2 * GTILE;
        const uint32_t* B = A + GTILE;
#pragma unroll
        for (int st = 0; st < 2; st++) {
            const int ko = 8 * st;
            uint32_t a[4][4], b[4][2];
#pragma unroll
            for (int mi = 0; mi < 4; mi++) {
                const int r = wm + mi * 16 + grp;
                a[mi][0] = A[r * GSTR + ko + q];
                a[mi][1] = A[(r + 8) * GSTR + ko + q];
                a[mi][2] = A[r * GSTR + ko + q + 4];
                a[mi][3] = A[(r + 8) * GSTR + ko + q + 4];
            }
#pragma unroll
            for (int ni = 0; ni < 4; ni++) {
                const int n = wn + ni * 8 + grp;
                b[ni][0] = B[n * GSTR + ko + q];
                b[ni][1] = B[n * GSTR + ko + q + 4];
            }
#pragma unroll
            for (int mi = 0; mi < 4; mi++)
#pragma unroll
                for (int ni = 0; ni < 4; ni++)
                    mma_f16(acc[mi][ni], a[mi], b[ni]);
        }

        if (kt + 2 < nk) issue_stage((kt + 2) % GSTAGES, (kt + 2) * GBK);
        CPA_COMMIT();
        stage = (stage + 1) % GSTAGES;
    }

#pragma unroll
    for (int mi = 0; mi < 4; mi++) {
#pragma unroll
        for (int half = 0; half < 2; half++) {
            const int gm = bm + wm + mi * 16 + grp + half * 8;
            if (gm >= MT) continue;
            const int bb = gm / NN;
            const int nn = gm - bb * NN;
#pragma unroll
            for (int ni = 0; ni < 4; ni++) {
                const int gn = bn + wn + ni * 8 + 2 * q;
                const float ox = acc[mi][ni][half * 2 + 0] + bias[gn];
                const float oy = acc[mi][ni][half * 2 + 1] + bias[gn + 1];
                if (MODE == 0) {
                    float2 o; o.x = ox; o.y = oy;
                    *reinterpret_cast<float2*>((float*)Yv + (size_t)gm * DD + gn) = o;
                } else {
                    const int h  = gn >> 6;
                    const int hd = gn & 63;
                    *reinterpret_cast<__half2*>(
                        (__half*)Yv + (((size_t)(bb * HH + h)) * NN + nn) * HDIM + hd)
                        = __floats2half2_rn(ox, oy);
                }
            }
        }
    }
}

// ---------------- RoPE on fp16 q and k ----------------
__global__ __launch_bounds__(256)
void rope_kernel(const float* __restrict__ sinp, const float* __restrict__ cosp)
{
    const int idx = blockIdx.x * blockDim.x + threadIdx.x;
    const int total = BB * HH * NP * 16;
    if (idx >= total) return;
    const int d2 = idx & 15;
    const int r  = idx >> 4;
    const int n  = r % NP;
    const int bh = r / NP;
    const size_t base = ((size_t)bh * NN + (n + PREFIX)) * HDIM;
    const int d = 2 * d2;

    const float2 c1 = *reinterpret_cast<const float2*>(cosp + n * HDIM + d);
    const float2 c2 = *reinterpret_cast<const float2*>(cosp + n * HDIM + d + 32);
    const float2 s1 = *reinterpret_cast<const float2*>(sinp + n * HDIM + d);
    const float2 s2 = *reinterpret_cast<const float2*>(sinp + n * HDIM + d + 32);

    {
        const float2 q1 = __half22float2(*reinterpret_cast<__half2*>(g_q + base + d));
        const float2 q2 = __half22float2(*reinterpret_cast<__half2*>(g_q + base + d + 32));
        *reinterpret_cast<__half2*>(g_q + base + d) =
            __floats2half2_rn(q1.x * c1.x - q2.x * s1.x, q1.y * c1.y - q2.y * s1.y);
        *reinterpret_cast<__half2*>(g_q + base + d + 32) =
            __floats2half2_rn(q2.x * c2.x + q1.x * s2.x, q2.y * c2.y + q1.y * s2.y);
    }
    {
        const float2 k1 = __half22float2(*reinterpret_cast<__half2*>(g_k + base + d));
        const float2 k2 = __half22float2(*reinterpret_cast<__half2*>(g_k + base + d + 32));
        *reinterpret_cast<__half2*>(g_k + base + d) =
            __floats2half2_rn(k1.x * c1.x - k2.x * s1.x, k1.y * c1.y - k2.y * s1.y);
        *reinterpret_cast<__half2*>(g_k + base + d + 32) =
            __floats2half2_rn(k2.x * c2.x + k1.x * s2.x, k2.y * c2.y + k1.y * s2.y);
    }
}

// ---------------- fp16 tensor-core flash attention ----------------
// 128 q-rows/CTA, 64 k-rows/tile, 8 warps x 16 q-rows. 3-stage cp.async
// K+V pipeline, all fragments via ldmatrix, Q fragments preloaded to regs,
// V row-major + ldmatrix.trans (no manual transpose), P register-resident.
#define AQ 128
#define AKT 64
#define ASTR32 36                       // 144B row stride
#define KV_U32 (AKT*ASTR32)             // 2304 u32 per matrix
#define STAGE_U32 (2*KV_U32)            // K+V per stage
#define Q_U32 (AQ*ASTR32)               // 4608 u32
#define ATTN_SMEM ((Q_U32 + 3*STAGE_U32)*4)   // 73728 bytes

__global__ __launch_bounds__(256, 2)
void attn_f16_kernel(__half* __restrict__ ctx)
{
    extern __shared__ uint32_t sma[];
    const uint32_t sb = (uint32_t)__cvta_generic_to_shared(sma);

    const int tid  = threadIdx.x;
    const int lane = tid & 31;
    const int warp = tid >> 5;
    const int q    = lane & 3;
    const int grp  = lane >> 2;
    const int bh   = blockIdx.y;
    const int q0   = blockIdx.x * AQ;

    const __half* __restrict__ Qg = g_q + (size_t)bh * NN * HDIM;
    const __half* __restrict__ Kg = g_k + (size_t)bh * NN * HDIM;
    const __half* __restrict__ Vg = g_v + (size_t)bh * NN * HDIM;

    // ldmatrix lane-address components
    const int l7  = lane & 7;
    const int l8  = (lane & 8) ? 1 : 0;
    const int l16 = (lane & 16) ? 1 : 0;

    // ---- issue Q (group 0) ----
#pragma unroll
    for (int it = 0; it < 4; it++) {
        const int c  = tid + it * 256;
        const int r  = c >> 3;
        const int k8 = (c & 7) * 8;
        cpa16(sb + (r * ASTR32 + (c & 7) * 4) * 4,
              Qg + (size_t)(q0 + r) * HDIM + k8, q0 + r < NN);
    }
    CPA_COMMIT();

    auto issue_kv = [&](int s, int k0) {
        const uint32_t kb = sb + (Q_U32 + s * STAGE_U32) * 4;
        const uint32_t vb = kb + KV_U32 * 4;
#pragma unroll
        for (int it = 0; it < 2; it++) {
            const int c   = tid + it * 256;
            const int ktr = c >> 3;
            const int k8  = (c & 7) * 8;
            const int du  = (ktr * ASTR32 + (c & 7) * 4) * 4;
            const bool p  = (k0 + ktr) < NN;
            cpa16(kb + du, Kg + (size_t)(k0 + ktr) * HDIM + k8, p);
            cpa16(vb + du, Vg + (size_t)(k0 + ktr) * HDIM + k8, p);
        }
    };

    issue_kv(0, 0);     CPA_COMMIT();
    issue_kv(1, AKT);   CPA_COMMIT();

    // ---- preload Q fragments (loop-invariant) ----
    CPA_WAIT(2);        // Q group done
    __syncthreads();
    uint32_t qa[4][4];
#pragma unroll
    for (int ks = 0; ks < 4; ks++) {
        const int row = warp * 16 + l7 + l8 * 8;
        const int col = 8 * ks + l16 * 4;
        ldsm_x4(qa[ks], sb + (row * ASTR32 + col) * 4);
    }

    float m0 = -INFINITY, m1 = -INFINITY, l0 = 0.f, l1 = 0.f;
    float acc_o[8][4];
#pragma unroll
    for (int nt = 0; nt < 8; nt++)
#pragma unroll
        for (int c = 0; c < 4; c++) acc_o[nt][c] = 0.f;

    const float scale = 0.125f;
    const int nkt = (NN + AKT - 1) / AKT;       // 17

    for (int t = 0; t < nkt; t++) {
        const int k0 = t * AKT;
        CPA_WAIT(1);        // stage t complete
        __syncthreads();

        const uint32_t kb = sb + (Q_U32 + (t % 3) * STAGE_U32) * 4;
        const uint32_t vb = kb + KV_U32 * 4;

        // ---- S = Q K^T ----
        float acc_s[8][4];
#pragma unroll
        for (int nt = 0; nt < 8; nt++)
#pragma unroll
            for (int c = 0; c < 4; c++) acc_s[nt][c] = 0.f;

#pragma unroll
        for (int ks = 0; ks < 4; ks++) {
#pragma unroll
            for (int np = 0; np < 4; np++) {
                // K b-frags: rows = kt, non-trans
                const int row = np * 16 + l7 + l16 * 8;
                const int col = 8 * ks + l8 * 4;
                uint32_t b[4];
                ldsm_x4(b, kb + (row * ASTR32 + col) * 4);
                mma_f16(acc_s[2 * np],     qa[ks], b);
                mma_f16(acc_s[2 * np + 1], qa[ks], b + 2);
            }
        }

        // ---- online softmax (fp32) ----
        float r0m = -INFINITY, r1m = -INFINITY;
#pragma unroll
        for (int nt = 0; nt < 8; nt++) {
            const int c = k0 + nt * 8 + 2 * q;
            const float s0 = (c     < NN) ? acc_s[nt][0] * scale : -INFINITY;
            const float s1 = (c + 1 < NN) ? acc_s[nt][1] * scale : -INFINITY;
            const float s2 = (c     < NN) ? acc_s[nt][2] * scale : -INFINITY;
            const float s3 = (c + 1 < NN) ? acc_s[nt][3] * scale : -INFINITY;
            acc_s[nt][0] = s0; acc_s[nt][1] = s1;
            acc_s[nt][2] = s2; acc_s[nt][3] = s3;
            r0m = fmaxf(r0m, fmaxf(s0, s1));
            r1m = fmaxf(r1m, fmaxf(s2, s3));
        }
        r0m = fmaxf(r0m, __shfl_xor_sync(0xffffffffu, r0m, 1));
        r0m = fmaxf(r0m, __shfl_xor_sync(0xffffffffu, r0m, 2));
        r1m = fmaxf(r1m, __shfl_xor_sync(0xffffffffu, r1m, 1));
        r1m = fmaxf(r1m, __shfl_xor_sync(0xffffffffu, r1m, 2));

        const float m0n = fmaxf(m0, r0m);
        const float m1n = fmaxf(m1, r1m);
        const float a0  = __expf(m0 - m0n);
        const float a1  = __expf(m1 - m1n);

        float sum0 = 0.f, sum1 = 0.f;
#pragma unroll
        for (int nt = 0; nt < 8; nt++) {
            const float p0 = __expf(acc_s[nt][0] - m0n);
            const float p1 = __expf(acc_s[nt][1] - m0n);
            const float p2 = __expf(acc_s[nt][2] - m1n);
            const float p3 = __expf(acc_s[nt][3] - m1n);
            acc_s[nt][0] = p0; acc_s[nt][1] = p1;
            acc_s[nt][2] = p2; acc_s[nt][3] = p3;
            sum0 += p0 + p1; sum1 += p2 + p3;
        }
        sum0 += __shfl_xor_sync(0xffffffffu, sum0, 1);
        sum0 += __shfl_xor_sync(0xffffffffu, sum0, 2);
        sum1 += __shfl_xor_sync(0xffffffffu, sum1, 1);
        sum1 += __shfl_xor_sync(0xffffffffu, sum1, 2);

        l0 = l0 * a0 + sum0;
        l1 = l1 * a1 + sum1;
        m0 = m0n; m1 = m1n;

#pragma unroll
        for (int nt = 0; nt < 8; nt++) {
            acc_o[nt][0] *= a0; acc_o[nt][1] *= a0;
            acc_o[nt][2] *= a1; acc_o[nt][3] *= a1;
        }

        // ---- O += P V (V row-major, ldmatrix.trans) ----
#pragma unroll
        for (int ks = 0; ks < 4; ks++) {
            uint32_t a[4];
            a[0] = fpack(acc_s[2 * ks][0],     acc_s[2 * ks][1]);
            a[1] = fpack(acc_s[2 * ks][2],     acc_s[2 * ks][3]);
            a[2] = fpack(acc_s[2 * ks + 1][0], acc_s[2 * ks + 1][1]);
            a[3] = fpack(acc_s[2 * ks + 1][2], acc_s[2 * ks + 1][3]);
#pragma unroll
            for (int np = 0; np < 4; np++) {
                // V b-frags: source rows = kt, cols = d block; trans
                const int row = 16 * ks + l7 + l8 * 8;
                const int col = 8 * np + l16 * 4;
                uint32_t b[4];
                ldsm_x4t(b, vb + (row * ASTR32 + col) * 4);
                mma_f16(acc_o[2 * np],     a, b);
                mma_f16(acc_o[2 * np + 1], a, b + 2);
            }
        }

        if (t + 2 < nkt) issue_kv((t + 2) % 3, (t + 2) * AKT);
        CPA_COMMIT();
    }

    // ---- epilogue: O / l -> ctx (half) ----
    const int b = bh / HH;
    const int h = bh % HH;
    const float inv0 = 1.f / l0;
    const float inv1 = 1.f / l1;
    const int r0g = q0 + warp * 16 + grp;
    const int r1g = r0g + 8;
#pragma unroll
    for (int nt = 0; nt < 8; nt++) {
        const int d = h * HDIM + nt * 8 + 2 * q;
        if (r0g < NN)
            *reinterpret_cast<__half2*>(ctx + ((size_t)(b * NN + r0g)) * DD + d)
                = __floats2half2_rn(acc_o[nt][0] * inv0, acc_o[nt][1] * inv0);
        if (r1g < NN)
            *reinterpret_cast<__half2*>(ctx + ((size_t)(b * NN + r1g)) * DD + d)
                = __floats2half2_rn(acc_o[nt][2] * inv1, acc_o[nt][3] * inv1);
    }
}

// ---------------- launch ----------------
extern "C" void kernel_launch(void* const* d_in, const int* in_sizes, int n_in,
                              void* d_out, int out_size)
{
    const float* hs  = (const float*)d_in[0];
    const float* sn  = (const float*)d_in[1];
    const float* cs  = (const float*)d_in[2];
    const float* Wq  = (const float*)d_in[3];
    const float* bq  = (const float*)d_in[4];
    const float* Wk  = (const float*)d_in[5];
    const float* bk  = (const float*)d_in[6];
    const float* Wv  = (const float*)d_in[7];
    const float* bv  = (const float*)d_in[8];
    const float* Wo  = (const float*)d_in[9];
    const float* bo  = (const float*)d_in[10];
    float* out = (float*)d_out;

    __half *hsh, *wqh, *wkh, *wvh, *woh, *qh, *kh, *vh, *ctxh;
    cudaGetSymbolAddress((void**)&hsh, g_hs);
    cudaGetSymbolAddress((void**)&wqh, g_wq);
    cudaGetSymbolAddress((void**)&wkh, g_wk);
    cudaGetSymbolAddress((void**)&wvh, g_wv);
    cudaGetSymbolAddress((void**)&woh, g_wo);
    cudaGetSymbolAddress((void**)&qh,  g_q);
    cudaGetSymbolAddress((void**)&kh,  g_k);
    cudaGetSymbolAddress((void**)&vh,  g_v);
    cudaGetSymbolAddress((void**)&ctxh, g_ctx);

    cudaFuncSetAttribute(gemm_f16_kernel<0>,
                         cudaFuncAttributeMaxDynamicSharedMemorySize, GEMM_SMEM);
    cudaFuncSetAttribute(gemm_f16_kernel<1>,
                         cudaFuncAttributeMaxDynamicSharedMemorySize, GEMM_SMEM);
    cudaFuncSetAttribute(attn_f16_kernel,
                         cudaFuncAttributeMaxDynamicSharedMemorySize, ATTN_SMEM);

    // convert inputs to fp16
    const int n4hs = MT * DD / 4;
    const int n4w  = DD * DD / 4;
    f2h_kernel<<<(n4hs + 255) / 256, 256>>>((const float4*)hs, (uint2*)hsh, n4hs);
    dim3 wgrid((n4w + 255) / 256, 4);
    f2h4_kernel<<<wgrid, 256>>>((const float4*)Wq, (const float4*)Wk,
                                (const float4*)Wv, (const float4*)Wo,
                                (uint2*)wqh, (uint2*)wkh, (uint2*)wvh, (uint2*)woh, n4w);

    const dim3 ggrid(DD / 128, (MT + 127) / 128);   // 8 x 129
    gemm_f16_kernel<1><<<ggrid, 256, GEMM_SMEM>>>(hsh, wqh, bq, qh);
    gemm_f16_kernel<1><<<ggrid, 256, GEMM_SMEM>>>(hsh, wkh, bk, kh);
    gemm_f16_kernel<1><<<ggrid, 256, GEMM_SMEM>>>(hsh, wvh, bv, vh);

    const int rope_threads = BB * HH * NP * 16;
    rope_kernel<<<(rope_threads + 255) / 256, 256>>>(sn, cs);

    const dim3 agrid((NN + AQ - 1) / AQ, BB * HH);  // 9 x 256
    attn_f16_kernel<<<agrid, 256, ATTN_SMEM>>>(ctxh);

    gemm_f16_kernel<0><<<ggrid, 256, GEMM_SMEM>>>(ctxh, woh, bo, out);
}

// round 16
// speedup vs baseline: 9.6350x; 1.0750x over previous
#include <cuda_runtime.h>
#include <cuda_fp16.h>
#include <math.h>
#include <stdint.h>

#define BB 16
#define NN 1029
#define HH 16
#define HDIM 64
#define DD 1024
#define MT (BB*NN)          // 16464 rows
#define NP 1024             // rope table length
#define PREFIX (NN-NP)      // 5

// ---------------- scratch (no allocations allowed) ----------------
__device__ __half g_hs[(size_t)MT*DD];
__device__ __half g_wq[(size_t)DD*DD];
__device__ __half g_wk[(size_t)DD*DD];
__device__ __half g_wv[(size_t)DD*DD];
__device__ __half g_wo[(size_t)DD*DD];
__device__ __half g_q[(size_t)BB*HH*NN*HDIM];
__device__ __half g_k[(size_t)BB*HH*NN*HDIM];
__device__ __half g_v[(size_t)BB*HH*NN*HDIM];
__device__ __half g_ctx[(size_t)BB*NN*DD];

// ---------------- helpers ----------------
__device__ __forceinline__ uint32_t fpack(float a, float b) {
    __half2 h = __floats2half2_rn(a, b);
    return *reinterpret_cast<uint32_t*>(&h);
}

__device__ __forceinline__ void mma_f16(float* d, const uint32_t* a, const uint32_t* b) {
    asm volatile(
        "mma.sync.aligned.m16n8k16.row.col.f32.f16.f16.f32 "
        "{%0,%1,%2,%3},{%4,%5,%6,%7},{%8,%9},{%0,%1,%2,%3};\n"
        : "+f"(d[0]), "+f"(d[1]), "+f"(d[2]), "+f"(d[3])
        : "r"(a[0]), "r"(a[1]), "r"(a[2]), "r"(a[3]), "r"(b[0]), "r"(b[1]));
}

__device__ __forceinline__ void cpa16(uint32_t dst, const void* src, bool p) {
    asm volatile("cp.async.ca.shared.global [%0], [%1], 16, %2;\n"
                 :: "r"(dst), "l"(src), "r"(p ? 16 : 0));
}
#define CPA_COMMIT() asm volatile("cp.async.commit_group;\n" ::: "memory")
#define CPA_WAIT(n)  asm volatile("cp.async.wait_group %0;\n" :: "n"(n) : "memory")

__device__ __forceinline__ void ldsm_x4(uint32_t* r, uint32_t addr) {
    asm volatile("ldmatrix.sync.aligned.m8n8.x4.shared.b16 {%0,%1,%2,%3}, [%4];\n"
                 : "=r"(r[0]), "=r"(r[1]), "=r"(r[2]), "=r"(r[3]) : "r"(addr));
}
__device__ __forceinline__ void ldsm_x4t(uint32_t* r, uint32_t addr) {
    asm volatile("ldmatrix.sync.aligned.m8n8.x4.trans.shared.b16 {%0,%1,%2,%3}, [%4];\n"
                 : "=r"(r[0]), "=r"(r[1]), "=r"(r[2]), "=r"(r[3]) : "r"(addr));
}

// ---------------- fp32 -> fp16 convert ----------------
__global__ __launch_bounds__(256)
void f2h_kernel(const float4* __restrict__ src, uint2* __restrict__ dst, int n4)
{
    const int i = blockIdx.x * blockDim.x + threadIdx.x;
    if (i >= n4) return;
    const float4 v = src[i];
    uint2 u;
    u.x = fpack(v.x, v.y);
    u.y = fpack(v.z, v.w);
    dst[i] = u;
}

__global__ __launch_bounds__(256)
void f2h4_kernel(const float4* s0, const float4* s1, const float4* s2, const float4* s3,
                 uint2* d0, uint2* d1, uint2* d2, uint2* d3, int n4)
{
    const int i = blockIdx.x * blockDim.x + threadIdx.x;
    if (i >= n4) return;
    const float4* s; uint2* d;
    switch (blockIdx.y) {
        case 0: s = s0; d = d0; break;
        case 1: s = s1; d = d1; break;
        case 2: s = s2; d = d2; break;
        default: s = s3; d = d3; break;
    }
    const float4 v = s[i];
    uint2 u;
    u.x = fpack(v.x, v.y);
    u.y = fpack(v.z, v.w);
    d[i] = u;
}

// ---------------- fp16 tensor-core GEMM, 3-stage cp.async + ldmatrix ----------------
#define GBK 32
#define GSTR 20
#define GTILE (128*GSTR)
#define GSTAGES 3
#define GEMM_SMEM (GSTAGES*2*GTILE*4)   // 61440 bytes

template<int MODE>
__global__ __launch_bounds__(256, 2)
void gemm_f16_kernel(const __half* __restrict__ X, const __half* __restrict__ W,
                     const float* __restrict__ bias, void* __restrict__ Yv)
{
    extern __shared__ uint32_t smg[];
    const uint32_t sbase = (uint32_t)__cvta_generic_to_shared(smg);

    const int tid  = threadIdx.x;
    const int lane = tid & 31;
    const int warp = tid >> 5;
    const int q    = lane & 3;
    const int grp  = lane >> 2;
    const int wm   = (warp >> 2) * 64;
    const int wn   = (warp & 3) * 32;

    const int bm = blockIdx.y * 128;
    const int bn = blockIdx.x * 128;

    // ldmatrix lane-address components
    const int l7  = lane & 7;
    const int l8  = (lane & 8) ? 1 : 0;
    const int l16 = (lane & 16) ? 1 : 0;

    // per-lane row byte offsets (constant over the loop)
    uint32_t arow[4];
#pragma unroll
    for (int mi = 0; mi < 4; mi++)
        arow[mi] = (uint32_t)((wm + mi * 16 + l7 + l8 * 8) * GSTR * 4);
    const uint32_t brow0 = (uint32_t)((wn +  0 + l7 + l16 * 8) * GSTR * 4);
    const uint32_t brow1 = (uint32_t)((wn + 16 + l7 + l16 * 8) * GSTR * 4);
    const uint32_t acol  = (uint32_t)(l16 * 16);   // (l16*4 u32)*4 bytes
    const uint32_t bcol  = (uint32_t)(l8 * 16);

    float acc[4][4][4];
#pragma unroll
    for (int mi = 0; mi < 4; mi++)
#pragma unroll
        for (int ni = 0; ni < 4; ni++)
#pragma unroll
            for (int c = 0; c < 4; c++) acc[mi][ni][c] = 0.f;

    auto issue_stage = [&](int st, int k0) {
#pragma unroll
        for (int it = 0; it < 2; it++) {
            const int c   = tid + it * 256;
            const int row = c >> 2;
            const int k8  = (c & 3) * 8;
            const int du  = row * GSTR + (c & 3) * 4;
            const int gm  = bm + row;
            cpa16(sbase + (st * 2 * GTILE + du) * 4,
                  X + (size_t)gm * DD + k0 + k8, gm < MT);
            cpa16(sbase + (st * 2 * GTILE + GTILE + du) * 4,
                  W + (size_t)(bn + row) * DD + k0 + k8, true);
        }
    };

    issue_stage(0, 0);  CPA_COMMIT();
    issue_stage(1, GBK); CPA_COMMIT();

    const int nk = DD / GBK;
    int stage = 0;

    for (int kt = 0; kt < nk; kt++) {
        CPA_WAIT(1);
        __syncthreads();

        const uint32_t abase = sbase + (stage * 2 * GTILE) * 4;
        const uint32_t bbase = abase + GTILE * 4;
#pragma unroll
        for (int st = 0; st < 2; st++) {
            const uint32_t ko = st * 32;         // 8 u32 = 32 bytes
            uint32_t a[4][4], b0[4], b1[4];
#pragma unroll
            for (int mi = 0; mi < 4; mi++)
                ldsm_x4(a[mi], abase + arow[mi] + ko + acol);
            ldsm_x4(b0, bbase + brow0 + ko + bcol);
            ldsm_x4(b1, bbase + brow1 + ko + bcol);
#pragma unroll
            for (int mi = 0; mi < 4; mi++) {
                mma_f16(acc[mi][0], a[mi], b0);
                mma_f16(acc[mi][1], a[mi], b0 + 2);
                mma_f16(acc[mi][2], a[mi], b1);
                mma_f16(acc[mi][3], a[mi], b1 + 2);
            }
        }

        if (kt + 2 < nk) issue_stage((kt + 2) % GSTAGES, (kt + 2) * GBK);
        CPA_COMMIT();
        stage = (stage + 1) % GSTAGES;
    }

#pragma unroll
    for (int mi = 0; mi < 4; mi++) {
#pragma unroll
        for (int half = 0; half < 2; half++) {
            const int gm = bm + wm + mi * 16 + grp + half * 8;
            if (gm >= MT) continue;
            const int bb = gm / NN;
            const int nn = gm - bb * NN;
#pragma unroll
            for (int ni = 0; ni < 4; ni++) {
                const int gn = bn + wn + ni * 8 + 2 * q;
                const float ox = acc[mi][ni][half * 2 + 0] + bias[gn];
                const float oy = acc[mi][ni][half * 2 + 1] + bias[gn + 1];
                if (MODE == 0) {
                    float2 o; o.x = ox; o.y = oy;
                    *reinterpret_cast<float2*>((float*)Yv + (size_t)gm * DD + gn) = o;
                } else {
                    const int h  = gn >> 6;
                    const int hd = gn & 63;
                    *reinterpret_cast<__half2*>(
                        (__half*)Yv + (((size_t)(bb * HH + h)) * NN + nn) * HDIM + hd)
                        = __floats2half2_rn(ox, oy);
                }
            }
        }
    }
}

// ---------------- RoPE on fp16 q and k ----------------
__global__ __launch_bounds__(256)
void rope_kernel(const float* __restrict__ sinp, const float* __restrict__ cosp)
{
    const int idx = blockIdx.x * blockDim.x + threadIdx.x;
    const int total = BB * HH * NP * 16;
    if (idx >= total) return;
    const int d2 = idx & 15;
    const int r  = idx >> 4;
    const int n  = r % NP;
    const int bh = r / NP;
    const size_t base = ((size_t)bh * NN + (n + PREFIX)) * HDIM;
    const int d = 2 * d2;

    const float2 c1 = *reinterpret_cast<const float2*>(cosp + n * HDIM + d);
    const float2 c2 = *reinterpret_cast<const float2*>(cosp + n * HDIM + d + 32);
    const float2 s1 = *reinterpret_cast<const float2*>(sinp + n * HDIM + d);
    const float2 s2 = *reinterpret_cast<const float2*>(sinp + n * HDIM + d + 32);

    {
        const float2 q1 = __half22float2(*reinterpret_cast<__half2*>(g_q + base + d));
        const float2 q2 = __half22float2(*reinterpret_cast<__half2*>(g_q + base + d + 32));
        *reinterpret_cast<__half2*>(g_q + base + d) =
            __floats2half2_rn(q1.x * c1.x - q2.x * s1.x, q1.y * c1.y - q2.y * s1.y);
        *reinterpret_cast<__half2*>(g_q + base + d + 32) =
            __floats2half2_rn(q2.x * c2.x + q1.x * s2.x, q2.y * c2.y + q1.y * s2.y);
    }
    {
        const float2 k1 = __half22float2(*reinterpret_cast<__half2*>(g_k + base + d));
        const float2 k2 = __half22float2(*reinterpret_cast<__half2*>(g_k + base + d + 32));
        *reinterpret_cast<__half2*>(g_k + base + d) =
            __floats2half2_rn(k1.x * c1.x - k2.x * s1.x, k1.y * c1.y - k2.y * s1.y);
        *reinterpret_cast<__half2*>(g_k + base + d + 32) =
            __floats2half2_rn(k2.x * c2.x + k1.x * s2.x, k2.y * c2.y + k1.y * s2.y);
    }
}

// ---------------- fp16 tensor-core flash attention ----------------
#define AQ 128
#define AKT 64
#define ASTR32 36
#define KV_U32 (AKT*ASTR32)
#define STAGE_U32 (2*KV_U32)
#define Q_U32 (AQ*ASTR32)
#define ATTN_SMEM ((Q_U32 + 3*STAGE_U32)*4)   // 73728 bytes

__global__ __launch_bounds__(256, 2)
void attn_f16_kernel(__half* __restrict__ ctx)
{
    extern __shared__ uint32_t sma[];
    const uint32_t sb = (uint32_t)__cvta_generic_to_shared(sma);

    const int tid  = threadIdx.x;
    const int lane = tid & 31;
    const int warp = tid >> 5;
    const int q    = lane & 3;
    const int grp  = lane >> 2;
    const int bh   = blockIdx.y;
    const int q0   = blockIdx.x * AQ;

    const __half* __restrict__ Qg = g_q + (size_t)bh * NN * HDIM;
    const __half* __restrict__ Kg = g_k + (size_t)bh * NN * HDIM;
    const __half* __restrict__ Vg = g_v + (size_t)bh * NN * HDIM;

    const int l7  = lane & 7;
    const int l8  = (lane & 8) ? 1 : 0;
    const int l16 = (lane & 16) ? 1 : 0;

#pragma unroll
    for (int it = 0; it < 4; it++) {
        const int c  = tid + it * 256;
        const int r  = c >> 3;
        const int k8 = (c & 7) * 8;
        cpa16(sb + (r * ASTR32 + (c & 7) * 4) * 4,
              Qg + (size_t)(q0 + r) * HDIM + k8, q0 + r < NN);
    }
    CPA_COMMIT();

    auto issue_kv = [&](int s, int k0) {
        const uint32_t kb = sb + (Q_U32 + s * STAGE_U32) * 4;
        const uint32_t vb = kb + KV_U32 * 4;
#pragma unroll
        for (int it = 0; it < 2; it++) {
            const int c   = tid + it * 256;
            const int ktr = c >> 3;
            const int k8  = (c & 7) * 8;
            const int du  = (ktr * ASTR32 + (c & 7) * 4) * 4;
            const bool p  = (k0 + ktr) < NN;
            cpa16(kb + du, Kg + (size_t)(k0 + ktr) * HDIM + k8, p);
            cpa16(vb + du, Vg + (size_t)(k0 + ktr) * HDIM + k8, p);
        }
    };

    issue_kv(0, 0);     CPA_COMMIT();
    issue_kv(1, AKT);   CPA_COMMIT();

    CPA_WAIT(2);
    __syncthreads();
    uint32_t qa[4][4];
#pragma unroll
    for (int ks = 0; ks < 4; ks++) {
        const int row = warp * 16 + l7 + l8 * 8;
        const int col = 8 * ks + l16 * 4;
        ldsm_x4(qa[ks], sb + (row * ASTR32 + col) * 4);
    }

    float m0 = -INFINITY, m1 = -INFINITY, l0 = 0.f, l1 = 0.f;
    float acc_o[8][4];
#pragma unroll
    for (int nt = 0; nt < 8; nt++)
#pragma unroll
        for (int c = 0; c < 4; c++) acc_o[nt][c] = 0.f;

    const float scale = 0.125f;
    const int nkt = (NN + AKT - 1) / AKT;       // 17

    for (int t = 0; t < nkt; t++) {
        const int k0 = t * AKT;
        CPA_WAIT(1);
        __syncthreads();

        const uint32_t kb = sb + (Q_U32 + (t % 3) * STAGE_U32) * 4;
        const uint32_t vb = kb + KV_U32 * 4;

        float acc_s[8][4];
#pragma unroll
        for (int nt = 0; nt < 8; nt++)
#pragma unroll
            for (int c = 0; c < 4; c++) acc_s[nt][c] = 0.f;

#pragma unroll
        for (int ks = 0; ks < 4; ks++) {
#pragma unroll
            for (int np = 0; np < 4; np++) {
                const int row = np * 16 + l7 + l16 * 8;
                const int col = 8 * ks + l8 * 4;
                uint32_t b[4];
                ldsm_x4(b, kb + (row * ASTR32 + col) * 4);
                mma_f16(acc_s[2 * np],     qa[ks], b);
                mma_f16(acc_s[2 * np + 1], qa[ks], b + 2);
            }
        }

        float r0m = -INFINITY, r1m = -INFINITY;
#pragma unroll
        for (int nt = 0; nt < 8; nt++) {
            const int c = k0 + nt * 8 + 2 * q;
            const float s0 = (c     < NN) ? acc_s[nt][0] * scale : -INFINITY;
            const float s1 = (c + 1 < NN) ? acc_s[nt][1] * scale : -INFINITY;
            const float s2 = (c     < NN) ? acc_s[nt][2] * scale : -INFINITY;
            const float s3 = (c + 1 < NN) ? acc_s[nt][3] * scale : -INFINITY;
            acc_s[nt][0] = s0; acc_s[nt][1] = s1;
            acc_s[nt][2] = s2; acc_s[nt][3] = s3;
            r0m = fmaxf(r0m, fmaxf(s0, s1));
            r1m = fmaxf(r1m, fmaxf(s2, s3));
        }
        r0m = fmaxf(r0m, __shfl_xor_sync(0xffffffffu, r0m, 1));
        r0m = fmaxf(r0m, __shfl_xor_sync(0xffffffffu, r0m, 2));
        r1m = fmaxf(r1m, __shfl_xor_sync(0xffffffffu, r1m, 1));
        r1m = fmaxf(r1m, __shfl_xor_sync(0xffffffffu, r1m, 2));

        const float m0n = fmaxf(m0, r0m);
        const float m1n = fmaxf(m1, r1m);
        const float a0  = __expf(m0 - m0n);
        const float a1  = __expf(m1 - m1n);

        float sum0 = 0.f, sum1 = 0.f;
#pragma unroll
        for (int nt = 0; nt < 8; nt++) {
            const float p0 = __expf(acc_s[nt][0] - m0n);
            const float p1 = __expf(acc_s[nt][1] - m0n);
            const float p2 = __expf(acc_s[nt][2] - m1n);
            const float p3 = __expf(acc_s[nt][3] - m1n);
            acc_s[nt][0] = p0; acc_s[nt][1] = p1;
            acc_s[nt][2] = p2; acc_s[nt][3] = p3;
            sum0 += p0 + p1; sum1 += p2 + p3;
        }
        sum0 += __shfl_xor_sync(0xffffffffu, sum0, 1);
        sum0 += __shfl_xor_sync(0xffffffffu, sum0, 2);
        sum1 += __shfl_xor_sync(0xffffffffu, sum1, 1);
        sum1 += __shfl_xor_sync(0xffffffffu, sum1, 2);

        l0 = l0 * a0 + sum0;
        l1 = l1 * a1 + sum1;
        m0 = m0n; m1 = m1n;

#pragma unroll
        for (int nt = 0; nt < 8; nt++) {
            acc_o[nt][0] *= a0; acc_o[nt][1] *= a0;
            acc_o[nt][2] *= a1; acc_o[nt][3] *= a1;
        }

#pragma unroll
        for (int ks = 0; ks < 4; ks++) {
            uint32_t a[4];
            a[0] = fpack(acc_s[2 * ks][0],     acc_s[2 * ks][1]);
            a[1] = fpack(acc_s[2 * ks][2],     acc_s[2 * ks][3]);
            a[2] = fpack(acc_s[2 * ks + 1][0], acc_s[2 * ks + 1][1]);
            a[3] = fpack(acc_s[2 * ks + 1][2], acc_s[2 * ks + 1][3]);
#pragma unroll
            for (int np = 0; np < 4; np++) {
                const int row = 16 * ks + l7 + l8 * 8;
                const int col = 8 * np + l16 * 4;
                uint32_t b[4];
                ldsm_x4t(b, vb + (row * ASTR32 + col) * 4);
                mma_f16(acc_o[2 * np],     a, b);
                mma_f16(acc_o[2 * np + 1], a, b + 2);
            }
        }

        if (t + 2 < nkt) issue_kv((t + 2) % 3, (t + 2) * AKT);
        CPA_COMMIT();
    }

    const int b = bh / HH;
    const int h = bh % HH;
    const float inv0 = 1.f / l0;
    const float inv1 = 1.f / l1;
    const int r0g = q0 + warp * 16 + grp;
    const int r1g = r0g + 8;
#pragma unroll
    for (int nt = 0; nt < 8; nt++) {
        const int d = h * HDIM + nt * 8 + 2 * q;
        if (r0g < NN)
            *reinterpret_cast<__half2*>(ctx + ((size_t)(b * NN + r0g)) * DD + d)
                = __floats2half2_rn(acc_o[nt][0] * inv0, acc_o[nt][1] * inv0);
        if (r1g < NN)
            *reinterpret_cast<__half2*>(ctx + ((size_t)(b * NN + r1g)) * DD + d)
                = __floats2half2_rn(acc_o[nt][2] * inv1, acc_o[nt][3] * inv1);
    }
}

// ---------------- launch ----------------
extern "C" void kernel_launch(void* const* d_in, const int* in_sizes, int n_in,
                              void* d_out, int out_size)
{
    const float* hs  = (const float*)d_in[0];
    const float* sn  = (const float*)d_in[1];
    const float* cs  = (const float*)d_in[2];
    const float* Wq  = (const float*)d_in[3];
    const float* bq  = (const float*)d_in[4];
    const float* Wk  = (const float*)d_in[5];
    const float* bk  = (const float*)d_in[6];
    const float* Wv  = (const float*)d_in[7];
    const float* bv  = (const float*)d_in[8];
    const float* Wo  = (const float*)d_in[9];
    const float* bo  = (const float*)d_in[10];
    float* out = (float*)d_out;

    __half *hsh, *wqh, *wkh, *wvh, *woh, *qh, *kh, *vh, *ctxh;
    cudaGetSymbolAddress((void**)&hsh, g_hs);
    cudaGetSymbolAddress((void**)&wqh, g_wq);
    cudaGetSymbolAddress((void**)&wkh, g_wk);
    cudaGetSymbolAddress((void**)&wvh, g_wv);
    cudaGetSymbolAddress((void**)&woh, g_wo);
    cudaGetSymbolAddress((void**)&qh,  g_q);
    cudaGetSymbolAddress((void**)&kh,  g_k);
    cudaGetSymbolAddress((void**)&vh,  g_v);
    cudaGetSymbolAddress((void**)&ctxh, g_ctx);

    cudaFuncSetAttribute(gemm_f16_kernel<0>,
                         cudaFuncAttributeMaxDynamicSharedMemorySize, GEMM_SMEM);
    cudaFuncSetAttribute(gemm_f16_kernel<1>,
                         cudaFuncAttributeMaxDynamicSharedMemorySize, GEMM_SMEM);
    cudaFuncSetAttribute(attn_f16_kernel,
                         cudaFuncAttributeMaxDynamicSharedMemorySize, ATTN_SMEM);

    const int n4hs = MT * DD / 4;
    const int n4w  = DD * DD / 4;
    f2h_kernel<<<(n4hs + 255) / 256, 256>>>((const float4*)hs, (uint2*)hsh, n4hs);
    dim3 wgrid((n4w + 255) / 256, 4);
    f2h4_kernel<<<wgrid, 256>>>((const float4*)Wq, (const float4*)Wk,
                                (const float4*)Wv, (const float4*)Wo,
                                (uint2*)wqh, (uint2*)wkh, (uint2*)wvh, (uint2*)woh, n4w);

    const dim3 ggrid(DD / 128, (MT + 127) / 128);   // 8 x 129
    gemm_f16_kernel<1><<<ggrid, 256, GEMM_SMEM>>>(hsh, wqh, bq, qh);
    gemm_f16_kernel<1><<<ggrid, 256, GEMM_SMEM>>>(hsh, wkh, bk, kh);
    gemm_f16_kernel<1><<<ggrid, 256, GEMM_SMEM>>>(hsh, wvh, bv, vh);

    const int rope_threads = BB * HH * NP * 16;
    rope_kernel<<<(rope_threads + 255) / 256, 256>>>(sn, cs);

    const dim3 agrid((NN + AQ - 1) / AQ, BB * HH);  // 9 x 256
    attn_f16_kernel<<<agrid, 256, ATTN_SMEM>>>(ctxh);

    gemm_f16_kernel<0><<<ggrid, 256, GEMM_SMEM>>>(ctxh, woh, bo, out);
}

// round 17
// speedup vs baseline: 10.2970x; 1.0687x over previous
#include <cuda_runtime.h>
#include <cuda_fp16.h>
#include <math.h>
#include <stdint.h>

#define BB 16
#define NN 1029
#define HH 16
#define HDIM 64
#define DD 1024
#define MT (BB*NN)          // 16464 rows
#define NP 1024             // rope table length
#define PREFIX (NN-NP)      // 5

// ---------------- scratch (no allocations allowed) ----------------
__device__ __half g_hs[(size_t)MT*DD];
__device__ __half g_wq[(size_t)DD*DD];
__device__ __half g_wk[(size_t)DD*DD];
__device__ __half g_wv[(size_t)DD*DD];
__device__ __half g_wo[(size_t)DD*DD];
__device__ __half g_q[(size_t)BB*HH*NN*HDIM];
__device__ __half g_k[(size_t)BB*HH*NN*HDIM];
__device__ __half g_v[(size_t)BB*HH*NN*HDIM];
__device__ __half g_ctx[(size_t)BB*NN*DD];

// ---------------- helpers ----------------
__device__ __forceinline__ uint32_t fpack(float a, float b) {
    __half2 h = __floats2half2_rn(a, b);
    return *reinterpret_cast<uint32_t*>(&h);
}

__device__ __forceinline__ void mma_f16(float* d, const uint32_t* a, const uint32_t* b) {
    asm volatile(
        "mma.sync.aligned.m16n8k16.row.col.f32.f16.f16.f32 "
        "{%0,%1,%2,%3},{%4,%5,%6,%7},{%8,%9},{%0,%1,%2,%3};\n"
        : "+f"(d[0]), "+f"(d[1]), "+f"(d[2]), "+f"(d[3])
        : "r"(a[0]), "r"(a[1]), "r"(a[2]), "r"(a[3]), "r"(b[0]), "r"(b[1]));
}

__device__ __forceinline__ void cpa16(uint32_t dst, const void* src, bool p) {
    asm volatile("cp.async.ca.shared.global [%0], [%1], 16, %2;\n"
                 :: "r"(dst), "l"(src), "r"(p ? 16 : 0));
}
#define CPA_COMMIT() asm volatile("cp.async.commit_group;\n" ::: "memory")
#define CPA_WAIT(n)  asm volatile("cp.async.wait_group %0;\n" :: "n"(n) : "memory")

__device__ __forceinline__ void ldsm_x4(uint32_t* r, uint32_t addr) {
    asm volatile("ldmatrix.sync.aligned.m8n8.x4.shared.b16 {%0,%1,%2,%3}, [%4];\n"
                 : "=r"(r[0]), "=r"(r[1]), "=r"(r[2]), "=r"(r[3]) : "r"(addr));
}
__device__ __forceinline__ void ldsm_x4t(uint32_t* r, uint32_t addr) {
    asm volatile("ldmatrix.sync.aligned.m8n8.x4.trans.shared.b16 {%0,%1,%2,%3}, [%4];\n"
                 : "=r"(r[0]), "=r"(r[1]), "=r"(r[2]), "=r"(r[3]) : "r"(addr));
}

// ---------------- fp32 -> fp16 convert ----------------
__global__ __launch_bounds__(256)
void f2h_kernel(const float4* __restrict__ src, uint2* __restrict__ dst, int n4)
{
    const int i = blockIdx.x * blockDim.x + threadIdx.x;
    if (i >= n4) return;
    const float4 v = src[i];
    uint2 u;
    u.x = fpack(v.x, v.y);
    u.y = fpack(v.z, v.w);
    dst[i] = u;
}

__global__ __launch_bounds__(256)
void f2h4_kernel(const float4* s0, const float4* s1, const float4* s2, const float4* s3,
                 uint2* d0, uint2* d1, uint2* d2, uint2* d3, int n4)
{
    const int i = blockIdx.x * blockDim.x + threadIdx.x;
    if (i >= n4) return;
    const float4* s; uint2* d;
    switch (blockIdx.y) {
        case 0: s = s0; d = d0; break;
        case 1: s = s1; d = d1; break;
        case 2: s = s2; d = d2; break;
        default: s = s3; d = d3; break;
    }
    const float4 v = s[i];
    uint2 u;
    u.x = fpack(v.x, v.y);
    u.y = fpack(v.z, v.w);
    d[i] = u;
}

// ---------------- fp16 tensor-core GEMM ----------------
// CTA 128x128, 4 warps (2x2), warp tile 64x64. BK=32, 3-stage cp.async,
// all fragments via ldmatrix. 8 ldsm feed 32 mma per k16 step.
#define GBK 32
#define GSTR 20
#define GTILE (128*GSTR)
#define GSTAGES 3
#define GEMM_SMEM (GSTAGES*2*GTILE*4)   // 61440 bytes

template<int MODE>
__global__ __launch_bounds__(128, 2)
void gemm_f16_kernel(const __half* __restrict__ X, const __half* __restrict__ W,
                     const float* __restrict__ bias, void* __restrict__ Yv)
{
    extern __shared__ uint32_t smg[];
    const uint32_t sbase = (uint32_t)__cvta_generic_to_shared(smg);

    const int tid  = threadIdx.x;
    const int lane = tid & 31;
    const int warp = tid >> 5;          // 0..3
    const int q    = lane & 3;
    const int grp  = lane >> 2;
    const int wm   = (warp >> 1) * 64;
    const int wn   = (warp & 1) * 64;

    const int bm = blockIdx.y * 128;
    const int bn = blockIdx.x * 128;

    const int l7  = lane & 7;
    const int l8  = (lane & 8) ? 1 : 0;
    const int l16 = (lane & 16) ? 1 : 0;

    uint32_t arow[4], brow[4];
#pragma unroll
    for (int mi = 0; mi < 4; mi++)
        arow[mi] = (uint32_t)((wm + mi * 16 + l7 + l8 * 8) * GSTR * 4);
#pragma unroll
    for (int ni = 0; ni < 4; ni++)
        brow[ni] = (uint32_t)((wn + ni * 16 + l7 + l16 * 8) * GSTR * 4);
    const uint32_t acol = (uint32_t)(l16 * 16);
    const uint32_t bcol = (uint32_t)(l8 * 16);

    float acc[4][8][4];
#pragma unroll
    for (int mi = 0; mi < 4; mi++)
#pragma unroll
        for (int ni = 0; ni < 8; ni++)
#pragma unroll
            for (int c = 0; c < 4; c++) acc[mi][ni][c] = 0.f;

    // loader: per stage, A+B each 128 rows x 4 chunks of 16B -> 4 chunks/thread each
    auto issue_stage = [&](int st, int k0) {
#pragma unroll
        for (int it = 0; it < 4; it++) {
            const int c   = tid + it * 128;
            const int row = c >> 2;
            const int k8  = (c & 3) * 8;
            const int du  = row * GSTR + (c & 3) * 4;
            const int gm  = bm + row;
            cpa16(sbase + (st * 2 * GTILE + du) * 4,
                  X + (size_t)gm * DD + k0 + k8, gm < MT);
            cpa16(sbase + (st * 2 * GTILE + GTILE + du) * 4,
                  W + (size_t)(bn + row) * DD + k0 + k8, true);
        }
    };

    issue_stage(0, 0);  CPA_COMMIT();
    issue_stage(1, GBK); CPA_COMMIT();

    const int nk = DD / GBK;
    int stage = 0;

    for (int kt = 0; kt < nk; kt++) {
        CPA_WAIT(1);
        __syncthreads();

        const uint32_t abase = sbase + (stage * 2 * GTILE) * 4;
        const uint32_t bbase = abase + GTILE * 4;
#pragma unroll
        for (int st = 0; st < 2; st++) {
            const uint32_t ko = st * 32;         // 8 u32 = 32B
            uint32_t a[4][4], b[4][4];
#pragma unroll
            for (int mi = 0; mi < 4; mi++)
                ldsm_x4(a[mi], abase + arow[mi] + ko + acol);
#pragma unroll
            for (int ni = 0; ni < 4; ni++)
                ldsm_x4(b[ni], bbase + brow[ni] + ko + bcol);
#pragma unroll
            for (int mi = 0; mi < 4; mi++)
#pragma unroll
                for (int ni = 0; ni < 4; ni++) {
                    mma_f16(acc[mi][2 * ni],     a[mi], b[ni]);
                    mma_f16(acc[mi][2 * ni + 1], a[mi], b[ni] + 2);
                }
        }

        if (kt + 2 < nk) issue_stage((kt + 2) % GSTAGES, (kt + 2) * GBK);
        CPA_COMMIT();
        stage = (stage + 1) % GSTAGES;
    }

#pragma unroll
    for (int mi = 0; mi < 4; mi++) {
#pragma unroll
        for (int half = 0; half < 2; half++) {
            const int gm = bm + wm + mi * 16 + grp + half * 8;
            if (gm >= MT) continue;
            const int bb = gm / NN;
            const int nn = gm - bb * NN;
#pragma unroll
            for (int ni = 0; ni < 8; ni++) {
                const int gn = bn + wn + ni * 8 + 2 * q;
                const float ox = acc[mi][ni][half * 2 + 0] + bias[gn];
                const float oy = acc[mi][ni][half * 2 + 1] + bias[gn + 1];
                if (MODE == 0) {
                    float2 o; o.x = ox; o.y = oy;
                    *reinterpret_cast<float2*>((float*)Yv + (size_t)gm * DD + gn) = o;
                } else {
                    const int h  = gn >> 6;
                    const int hd = gn & 63;
                    *reinterpret_cast<__half2*>(
                        (__half*)Yv + (((size_t)(bb * HH + h)) * NN + nn) * HDIM + hd)
                        = __floats2half2_rn(ox, oy);
                }
            }
        }
    }
}

// ---------------- RoPE on fp16 q and k ----------------
__global__ __launch_bounds__(256)
void rope_kernel(const float* __restrict__ sinp, const float* __restrict__ cosp)
{
    const int idx = blockIdx.x * blockDim.x + threadIdx.x;
    const int total = BB * HH * NP * 16;
    if (idx >= total) return;
    const int d2 = idx & 15;
    const int r  = idx >> 4;
    const int n  = r % NP;
    const int bh = r / NP;
    const size_t base = ((size_t)bh * NN + (n + PREFIX)) * HDIM;
    const int d = 2 * d2;

    const float2 c1 = *reinterpret_cast<const float2*>(cosp + n * HDIM + d);
    const float2 c2 = *reinterpret_cast<const float2*>(cosp + n * HDIM + d + 32);
    const float2 s1 = *reinterpret_cast<const float2*>(sinp + n * HDIM + d);
    const float2 s2 = *reinterpret_cast<const float2*>(sinp + n * HDIM + d + 32);

    {
        const float2 q1 = __half22float2(*reinterpret_cast<__half2*>(g_q + base + d));
        const float2 q2 = __half22float2(*reinterpret_cast<__half2*>(g_q + base + d + 32));
        *reinterpret_cast<__half2*>(g_q + base + d) =
            __floats2half2_rn(q1.x * c1.x - q2.x * s1.x, q1.y * c1.y - q2.y * s1.y);
        *reinterpret_cast<__half2*>(g_q + base + d + 32) =
            __floats2half2_rn(q2.x * c2.x + q1.x * s2.x, q2.y * c2.y + q1.y * s2.y);
    }
    {
        const float2 k1 = __half22float2(*reinterpret_cast<__half2*>(g_k + base + d));
        const float2 k2 = __half22float2(*reinterpret_cast<__half2*>(g_k + base + d + 32));
        *reinterpret_cast<__half2*>(g_k + base + d) =
            __floats2half2_rn(k1.x * c1.x - k2.x * s1.x, k1.y * c1.y - k2.y * s1.y);
        *reinterpret_cast<__half2*>(g_k + base + d + 32) =
            __floats2half2_rn(k2.x * c2.x + k1.x * s2.x, k2.y * c2.y + k1.y * s2.y);
    }
}

// ---------------- fp16 tensor-core flash attention ----------------
#define AQ 128
#define AKT 64
#define ASTR32 36
#define KV_U32 (AKT*ASTR32)
#define STAGE_U32 (2*KV_U32)
#define Q_U32 (AQ*ASTR32)
#define ATTN_SMEM ((Q_U32 + 3*STAGE_U32)*4)   // 73728 bytes

__global__ __launch_bounds__(256, 2)
void attn_f16_kernel(__half* __restrict__ ctx)
{
    extern __shared__ uint32_t sma[];
    const uint32_t sb = (uint32_t)__cvta_generic_to_shared(sma);

    const int tid  = threadIdx.x;
    const int lane = tid & 31;
    const int warp = tid >> 5;
    const int q    = lane & 3;
    const int grp  = lane >> 2;
    const int bh   = blockIdx.y;
    const int q0   = blockIdx.x * AQ;

    const __half* __restrict__ Qg = g_q + (size_t)bh * NN * HDIM;
    const __half* __restrict__ Kg = g_k + (size_t)bh * NN * HDIM;
    const __half* __restrict__ Vg = g_v + (size_t)bh * NN * HDIM;

    const int l7  = lane & 7;
    const int l8  = (lane & 8) ? 1 : 0;
    const int l16 = (lane & 16) ? 1 : 0;

#pragma unroll
    for (int it = 0; it < 4; it++) {
        const int c  = tid + it * 256;
        const int r  = c >> 3;
        const int k8 = (c & 7) * 8;
        cpa16(sb + (r * ASTR32 + (c & 7) * 4) * 4,
              Qg + (size_t)(q0 + r) * HDIM + k8, q0 + r < NN);
    }
    CPA_COMMIT();

    auto issue_kv = [&](int s, int k0) {
        const uint32_t kb = sb + (Q_U32 + s * STAGE_U32) * 4;
        const uint32_t vb = kb + KV_U32 * 4;
#pragma unroll
        for (int it = 0; it < 2; it++) {
            const int c   = tid + it * 256;
            const int ktr = c >> 3;
            const int k8  = (c & 7) * 8;
            const int du  = (ktr * ASTR32 + (c & 7) * 4) * 4;
            const bool p  = (k0 + ktr) < NN;
            cpa16(kb + du, Kg + (size_t)(k0 + ktr) * HDIM + k8, p);
            cpa16(vb + du, Vg + (size_t)(k0 + ktr) * HDIM + k8, p);
        }
    };

    issue_kv(0, 0);     CPA_COMMIT();
    issue_kv(1, AKT);   CPA_COMMIT();

    CPA_WAIT(2);
    __syncthreads();
    uint32_t qa[4][4];
#pragma unroll
    for (int ks = 0; ks < 4; ks++) {
        const int row = warp * 16 + l7 + l8 * 8;
        const int col = 8 * ks + l16 * 4;
        ldsm_x4(qa[ks], sb + (row * ASTR32 + col) * 4);
    }

    float m0 = -INFINITY, m1 = -INFINITY, l0 = 0.f, l1 = 0.f;
    float acc_o[8][4];
#pragma unroll
    for (int nt = 0; nt < 8; nt++)
#pragma unroll
        for (int c = 0; c < 4; c++) acc_o[nt][c] = 0.f;

    const float scale = 0.125f;
    const int nkt = (NN + AKT - 1) / AKT;       // 17

    for (int t = 0; t < nkt; t++) {
        const int k0 = t * AKT;
        CPA_WAIT(1);
        __syncthreads();

        const uint32_t kb = sb + (Q_U32 + (t % 3) * STAGE_U32) * 4;
        const uint32_t vb = kb + KV_U32 * 4;

        float acc_s[8][4];
#pragma unroll
        for (int nt = 0; nt < 8; nt++)
#pragma unroll
            for (int c = 0; c < 4; c++) acc_s[nt][c] = 0.f;

#pragma unroll
        for (int ks = 0; ks < 4; ks++) {
#pragma unroll
            for (int np = 0; np < 4; np++) {
                const int row = np * 16 + l7 + l16 * 8;
                const int col = 8 * ks + l8 * 4;
                uint32_t b[4];
                ldsm_x4(b, kb + (row * ASTR32 + col) * 4);
                mma_f16(acc_s[2 * np],     qa[ks], b);
                mma_f16(acc_s[2 * np + 1], qa[ks], b + 2);
            }
        }

        float r0m = -INFINITY, r1m = -INFINITY;
#pragma unroll
        for (int nt = 0; nt < 8; nt++) {
            const int c = k0 + nt * 8 + 2 * q;
            const float s0 = (c     < NN) ? acc_s[nt][0] * scale : -INFINITY;
            const float s1 = (c + 1 < NN) ? acc_s[nt][1] * scale : -INFINITY;
            const float s2 = (c     < NN) ? acc_s[nt][2] * scale : -INFINITY;
            const float s3 = (c + 1 < NN) ? acc_s[nt][3] * scale : -INFINITY;
            acc_s[nt][0] = s0; acc_s[nt][1] = s1;
            acc_s[nt][2] = s2; acc_s[nt][3] = s3;
            r0m = fmaxf(r0m, fmaxf(s0, s1));
            r1m = fmaxf(r1m, fmaxf(s2, s3));
        }
        r0m = fmaxf(r0m, __shfl_xor_sync(0xffffffffu, r0m, 1));
        r0m = fmaxf(r0m, __shfl_xor_sync(0xffffffffu, r0m, 2));
        r1m = fmaxf(r1m, __shfl_xor_sync(0xffffffffu, r1m, 1));
        r1m = fmaxf(r1m, __shfl_xor_sync(0xffffffffu, r1m, 2));

        const float m0n = fmaxf(m0, r0m);
        const float m1n = fmaxf(m1, r1m);
        const float a0  = __expf(m0 - m0n);
        const float a1  = __expf(m1 - m1n);

        float sum0 = 0.f, sum1 = 0.f;
#pragma unroll
        for (int nt = 0; nt < 8; nt++) {
            const float p0 = __expf(acc_s[nt][0] - m0n);
            const float p1 = __expf(acc_s[nt][1] - m0n);
            const float p2 = __expf(acc_s[nt][2] - m1n);
            const float p3 = __expf(acc_s[nt][3] - m1n);
            acc_s[nt][0] = p0; acc_s[nt][1] = p1;
            acc_s[nt][2] = p2; acc_s[nt][3] = p3;
            sum0 += p0 + p1; sum1 += p2 + p3;
        }
        sum0 += __shfl_xor_sync(0xffffffffu, sum0, 1);
        sum0 += __shfl_xor_sync(0xffffffffu, sum0, 2);
        sum1 += __shfl_xor_sync(0xffffffffu, sum1, 1);
        sum1 += __shfl_xor_sync(0xffffffffu, sum1, 2);

        l0 = l0 * a0 + sum0;
        l1 = l1 * a1 + sum1;
        m0 = m0n; m1 = m1n;

#pragma unroll
        for (int nt = 0; nt < 8; nt++) {
            acc_o[nt][0] *= a0; acc_o[nt][1] *= a0;
            acc_o[nt][2] *= a1; acc_o[nt][3] *= a1;
        }

#pragma unroll
        for (int ks = 0; ks < 4; ks++) {
            uint32_t a[4];
            a[0] = fpack(acc_s[2 * ks][0],     acc_s[2 * ks][1]);
            a[1] = fpack(acc_s[2 * ks][2],     acc_s[2 * ks][3]);
            a[2] = fpack(acc_s[2 * ks + 1][0], acc_s[2 * ks + 1][1]);
            a[3] = fpack(acc_s[2 * ks + 1][2], acc_s[2 * ks + 1][3]);
#pragma unroll
            for (int np = 0; np < 4; np++) {
                const int row = 16 * ks + l7 + l8 * 8;
                const int col = 8 * np + l16 * 4;
                uint32_t b[4];
                ldsm_x4t(b, vb + (row * ASTR32 + col) * 4);
                mma_f16(acc_o[2 * np],     a, b);
                mma_f16(acc_o[2 * np + 1], a, b + 2);
            }
        }

        if (t + 2 < nkt) issue_kv((t + 2) % 3, (t + 2) * AKT);
        CPA_COMMIT();
    }

    const int b = bh / HH;
    const int h = bh % HH;
    const float inv0 = 1.f / l0;
    const float inv1 = 1.f / l1;
    const int r0g = q0 + warp * 16 + grp;
    const int r1g = r0g + 8;
#pragma unroll
    for (int nt = 0; nt < 8; nt++) {
        const int d = h * HDIM + nt * 8 + 2 * q;
        if (r0g < NN)
            *reinterpret_cast<__half2*>(ctx + ((size_t)(b * NN + r0g)) * DD + d)
                = __floats2half2_rn(acc_o[nt][0] * inv0, acc_o[nt][1] * inv0);
        if (r1g < NN)
            *reinterpret_cast<__half2*>(ctx + ((size_t)(b * NN + r1g)) * DD + d)
                = __floats2half2_rn(acc_o[nt][2] * inv1, acc_o[nt][3] * inv1);
    }
}

// ---------------- launch ----------------
extern "C" void kernel_launch(void* const* d_in, const int* in_sizes, int n_in,
                              void* d_out, int out_size)
{
    const float* hs  = (const float*)d_in[0];
    const float* sn  = (const float*)d_in[1];
    const float* cs  = (const float*)d_in[2];
    const float* Wq  = (const float*)d_in[3];
    const float* bq  = (const float*)d_in[4];
    const float* Wk  = (const float*)d_in[5];
    const float* bk  = (const float*)d_in[6];
    const float* Wv  = (const float*)d_in[7];
    const float* bv  = (const float*)d_in[8];
    const float* Wo  = (const float*)d_in[9];
    const float* bo  = (const float*)d_in[10];
    float* out = (float*)d_out;

    __half *hsh, *wqh, *wkh, *wvh, *woh, *qh, *kh, *vh, *ctxh;
    cudaGetSymbolAddress((void**)&hsh, g_hs);
    cudaGetSymbolAddress((void**)&wqh, g_wq);
    cudaGetSymbolAddress((void**)&wkh, g_wk);
    cudaGetSymbolAddress((void**)&wvh, g_wv);
    cudaGetSymbolAddress((void**)&woh, g_wo);
    cudaGetSymbolAddress((void**)&qh,  g_q);
    cudaGetSymbolAddress((void**)&kh,  g_k);
    cudaGetSymbolAddress((void**)&vh,  g_v);
    cudaGetSymbolAddress((void**)&ctxh, g_ctx);

    cudaFuncSetAttribute(gemm_f16_kernel<0>,
                         cudaFuncAttributeMaxDynamicSharedMemorySize, GEMM_SMEM);
    cudaFuncSetAttribute(gemm_f16_kernel<1>,
                         cudaFuncAttributeMaxDynamicSharedMemorySize, GEMM_SMEM);
    cudaFuncSetAttribute(attn_f16_kernel,
                         cudaFuncAttributeMaxDynamicSharedMemorySize, ATTN_SMEM);

    const int n4hs = MT * DD / 4;
    const int n4w  = DD * DD / 4;
    f2h_kernel<<<(n4hs + 255) / 256, 256>>>((const float4*)hs, (uint2*)hsh, n4hs);
    dim3 wgrid((n4w + 255) / 256, 4);
    f2h4_kernel<<<wgrid, 256>>>((const float4*)Wq, (const float4*)Wk,
                                (const float4*)Wv, (const float4*)Wo,
                                (uint2*)wqh, (uint2*)wkh, (uint2*)wvh, (uint2*)woh, n4w);

    const dim3 ggrid(DD / 128, (MT + 127) / 128);   // 8 x 129
    gemm_f16_kernel<1><<<ggrid, 128, GEMM_SMEM>>>(hsh, wqh, bq, qh);
    gemm_f16_kernel<1><<<ggrid, 128, GEMM_SMEM>>>(hsh, wkh, bk, kh);
    gemm_f16_kernel<1><<<ggrid, 128, GEMM_SMEM>>>(hsh, wvh, bv, vh);

    const int rope_threads = BB * HH * NP * 16;
    rope_kernel<<<(rope_threads + 255) / 256, 256>>>(sn, cs);

    const dim3 agrid((NN + AQ - 1) / AQ, BB * HH);  // 9 x 256
    attn_f16_kernel<<<agrid, 256, ATTN_SMEM>>>(ctxh);

    gemm_f16_kernel<0><<<ggrid, 128, GEMM_SMEM>>>(ctxh, woh, bo, out);
}